// round 1
// baseline (speedup 1.0000x reference)
#include <cuda_runtime.h>
#include <math.h>

// Problem constants
#define B 2
#define S 4096
#define HID 2048
#define NH 32
#define NKV 8
#define HD 64
#define GROUPS 4
#define BS_ROWS (B * S)   // 8192

// ---------------- scratch (static device globals; no allocation) ----------------
__device__ float g_q  [(size_t)B * S * NH  * HD];  // [B,S,NH,64]  (becomes Qk after rope+kappa)
__device__ float g_k  [(size_t)B * S * NKV * HD];  // [B,S,8,64]   (becomes Kk)
__device__ float g_v  [(size_t)B * S * NKV * HD];
__device__ float g_phi[(size_t)B * S * NH  * HD];
__device__ float g_ctx[(size_t)B * S * NH  * HD];
__device__ float g_Qg [B * NH * HD];
__device__ float g_logits[B * NH * S];
__device__ float g_alpha [B * NH * S];
__device__ float g_M  [B * NH * HD * HD];          // outer_sum state, [bh][d][f]

// ---------------- SGEMM: C[M,N] = A[M,K] @ B[K,N], row-major, 128x128x8 tiles ----------------
__global__ __launch_bounds__(256) void sgemm_kernel(const float* __restrict__ A,
                                                    const float* __restrict__ Bm,
                                                    float* __restrict__ C,
                                                    int M, int N, int K) {
    __shared__ float As[8][128];
    __shared__ float Bs[8][128];

    const int tid = threadIdx.x;
    const int bm = blockIdx.y * 128;
    const int bn = blockIdx.x * 128;

    const int tx = tid % 16;        // n direction
    const int ty = tid / 16;        // m direction
    const int tm = ty * 8;
    const int tn = tx * 8;

    // A tile load: 128 rows x 8 cols -> one float4 per thread
    const int a_row = tid / 2;
    const int a_col = (tid % 2) * 4;
    // B tile load: 8 rows x 128 cols -> one float4 per thread
    const int b_row = tid / 32;
    const int b_col = (tid % 32) * 4;

    float acc[8][8];
    #pragma unroll
    for (int i = 0; i < 8; i++)
        #pragma unroll
        for (int j = 0; j < 8; j++) acc[i][j] = 0.0f;

    for (int k0 = 0; k0 < K; k0 += 8) {
        float4 av = *(const float4*)&A[(size_t)(bm + a_row) * K + k0 + a_col];
        As[a_col + 0][a_row] = av.x;
        As[a_col + 1][a_row] = av.y;
        As[a_col + 2][a_row] = av.z;
        As[a_col + 3][a_row] = av.w;
        *(float4*)&Bs[b_row][b_col] =
            *(const float4*)&Bm[(size_t)(k0 + b_row) * N + bn + b_col];
        __syncthreads();

        #pragma unroll
        for (int kk = 0; kk < 8; kk++) {
            float ar[8], br[8];
            *(float4*)&ar[0] = *(float4*)&As[kk][tm];
            *(float4*)&ar[4] = *(float4*)&As[kk][tm + 4];
            *(float4*)&br[0] = *(float4*)&Bs[kk][tn];
            *(float4*)&br[4] = *(float4*)&Bs[kk][tn + 4];
            #pragma unroll
            for (int i = 0; i < 8; i++)
                #pragma unroll
                for (int j = 0; j < 8; j++)
                    acc[i][j] = fmaf(ar[i], br[j], acc[i][j]);
        }
        __syncthreads();
    }

    #pragma unroll
    for (int i = 0; i < 8; i++) {
        #pragma unroll
        for (int j = 0; j < 8; j += 4) {
            float4 v = make_float4(acc[i][j], acc[i][j + 1], acc[i][j + 2], acc[i][j + 3]);
            *(float4*)&C[(size_t)(bm + tm + i) * N + bn + tn + j] = v;
        }
    }
}

// ---------------- fused RoPE + kappa (elu+1), in place on [B,S,H,64] ----------------
__global__ void rope_kappa_kernel(float* __restrict__ x, int H, long total_pairs) {
    long idx = (long)blockIdx.x * blockDim.x + threadIdx.x;
    if (idx >= total_pairs) return;
    int j = (int)(idx & 31);
    long t = idx >> 5;
    int h = (int)(t % H); t /= H;
    int s = (int)(t % S);
    int b = (int)(t / S);

    // mirror jax fp32 pipeline: inv_freq = 1 / theta^(2j/64)
    float e = (float)(2 * j) / 64.0f;
    float invf = 1.0f / powf(10000.0f, e);
    float ang = (float)s * invf;
    float c, sn;
    sincosf(ang, &sn, &c);

    size_t base = (((size_t)b * S + s) * H + h) * 64;
    float x1 = x[base + j];
    float x2 = x[base + j + 32];
    float o1 = x1 * c - x2 * sn;
    float o2 = x2 * c + x1 * sn;
    // kappa = elu(x)+1 : x>0 ? x+1 : exp(x)
    o1 = (o1 > 0.0f) ? (o1 + 1.0f) : expf(o1);
    o2 = (o2 > 0.0f) ? (o2 + 1.0f) : expf(o2);
    x[base + j]      = o1;
    x[base + j + 32] = o2;
}

// ---------------- Qg = mean over S of Qk : [B,NH,64] ----------------
__global__ __launch_bounds__(256) void qg_kernel() {
    int bh = blockIdx.x;          // 0..63
    int b = bh / NH, h = bh % NH;
    int d  = threadIdx.x % 64;
    int sg = threadIdx.x / 64;    // 0..3
    float sum = 0.0f;
    for (int s = sg; s < S; s += 4)
        sum += g_q[(((size_t)b * S + s) * NH + h) * 64 + d];
    __shared__ float red[256];
    red[threadIdx.x] = sum;
    __syncthreads();
    if (sg == 0) {
        float tot = red[d] + red[64 + d] + red[128 + d] + red[192 + d];
        g_Qg[bh * 64 + d] = tot / (float)S;
    }
}

// ---------------- logits[b,h,s] = Qg[b,h,:] . Kk[b,s,h/4,:]  (warp per element) ----------------
__global__ __launch_bounds__(256) void logits_kernel() {
    int warp = (blockIdx.x * blockDim.x + threadIdx.x) >> 5;
    int lane = threadIdx.x & 31;
    int s = warp % S; int t = warp / S;
    int h = t % NH;   int b = t / NH;
    int hk = h / GROUPS;
    const float* krow = &g_k[(((size_t)b * S + s) * NKV + hk) * 64];
    const float* qrow = &g_Qg[(b * NH + h) * 64];
    float sum = krow[lane] * qrow[lane] + krow[lane + 32] * qrow[lane + 32];
    #pragma unroll
    for (int off = 16; off > 0; off >>= 1)
        sum += __shfl_xor_sync(0xffffffffu, sum, off);
    if (lane == 0)
        g_logits[((size_t)b * NH + h) * S + s] = sum;
}

// ---------------- alpha = softmax(logits) * S, per (b,h) row ----------------
__global__ __launch_bounds__(256) void softmax_kernel() {
    int bh = blockIdx.x;
    const float* row = &g_logits[(size_t)bh * S];
    __shared__ float red[256];
    float m = -INFINITY;
    for (int i = threadIdx.x; i < S; i += 256) m = fmaxf(m, row[i]);
    red[threadIdx.x] = m; __syncthreads();
    for (int st = 128; st > 0; st >>= 1) {
        if (threadIdx.x < st) red[threadIdx.x] = fmaxf(red[threadIdx.x], red[threadIdx.x + st]);
        __syncthreads();
    }
    m = red[0]; __syncthreads();
    float sum = 0.0f;
    for (int i = threadIdx.x; i < S; i += 256) sum += expf(row[i] - m);
    red[threadIdx.x] = sum; __syncthreads();
    for (int st = 128; st > 0; st >>= 1) {
        if (threadIdx.x < st) red[threadIdx.x] += red[threadIdx.x + st];
        __syncthreads();
    }
    float scale = (float)S / red[0];
    for (int i = threadIdx.x; i < S; i += 256)
        g_alpha[(size_t)bh * S + i] = expf(row[i] - m) * scale;
}

// ---------------- outer_sum[b,h,d,f] = sum_s alpha*Kk[d]*v[f]  (block per (b,h)) ----------------
__global__ __launch_bounds__(256) void outer_kernel() {
    int bh = blockIdx.x;
    int b = bh / NH, h = bh % NH, hk = h / GROUPS;
    __shared__ float Ws[32][64];   // alpha * Kk
    __shared__ float Vs[32][64];
    int f = threadIdx.x % 64;
    int g = threadIdx.x / 64;      // 0..3
    float acc[16];
    #pragma unroll
    for (int i = 0; i < 16; i++) acc[i] = 0.0f;

    for (int s0 = 0; s0 < S; s0 += 32) {
        __syncthreads();
        for (int i = threadIdx.x; i < 32 * 64; i += 256) {
            int s = i / 64, d = i % 64;
            size_t idx = (((size_t)b * S + s0 + s) * NKV + hk) * 64 + d;
            float a = g_alpha[((size_t)b * NH + h) * S + s0 + s];
            Ws[s][d] = a * g_k[idx];
            Vs[s][d] = g_v[idx];
        }
        __syncthreads();
        #pragma unroll 4
        for (int s = 0; s < 32; s++) {
            float vv = Vs[s][f];
            #pragma unroll
            for (int i = 0; i < 16; i++)
                acc[i] = fmaf(Ws[s][g + 4 * i], vv, acc[i]);
        }
    }
    #pragma unroll
    for (int i = 0; i < 16; i++) {
        int d = g + 4 * i;
        g_M[((size_t)bh * 64 + d) * 64 + f] = acc[i];
    }
}

// ---------------- ctx[b,s,h,f] = phi[b,s,h,f] * (Qk[b,s,h,:] . M[b,h,:,f]) ----------------
__global__ __launch_bounds__(256) void attnmul_kernel() {
    int bh = blockIdx.y;
    int b = bh / NH, h = bh % NH;
    int s0 = blockIdx.x * 64;
    __shared__ float Ms[64][64];
    __shared__ float Qs[64][64];
    for (int i = threadIdx.x; i < 64 * 64; i += 256) {
        Ms[i / 64][i % 64] = g_M[(size_t)bh * 4096 + i];
        int s = i / 64, d = i % 64;
        Qs[s][d] = g_q[(((size_t)b * S + s0 + s) * NH + h) * 64 + d];
    }
    __syncthreads();
    int f = threadIdx.x % 64;
    int sg = threadIdx.x / 64;
    for (int s = sg; s < 64; s += 4) {
        float acc = 0.0f;
        #pragma unroll
        for (int d = 0; d < 64; d++)
            acc = fmaf(Qs[s][d], Ms[d][f], acc);
        size_t idx = (((size_t)b * S + s0 + s) * NH + h) * 64 + f;
        g_ctx[idx] = g_phi[idx] * acc;
    }
}

// ---------------- host launcher ----------------
extern "C" void kernel_launch(void* const* d_in, const int* in_sizes, int n_in,
                              void* d_out, int out_size) {
    const float* hs   = (const float*)d_in[0];
    const float* Wq   = (const float*)d_in[1];
    const float* Wk   = (const float*)d_in[2];
    const float* Wv   = (const float*)d_in[3];
    const float* Wphi = (const float*)d_in[4];
    const float* Wo   = (const float*)d_in[5];
    float* out = (float*)d_out;

    float *q, *k, *v, *phi, *ctx;
    cudaGetSymbolAddress((void**)&q,   g_q);
    cudaGetSymbolAddress((void**)&k,   g_k);
    cudaGetSymbolAddress((void**)&v,   g_v);
    cudaGetSymbolAddress((void**)&phi, g_phi);
    cudaGetSymbolAddress((void**)&ctx, g_ctx);

    dim3 gBig(HID / 128, BS_ROWS / 128);   // (16, 64)
    dim3 gKV(512 / 128, BS_ROWS / 128);    // (4, 64)

    // projections
    sgemm_kernel<<<gBig, 256>>>(hs, Wq,   q,   BS_ROWS, NH * HD,  HID);
    sgemm_kernel<<<gKV,  256>>>(hs, Wk,   k,   BS_ROWS, NKV * HD, HID);
    sgemm_kernel<<<gKV,  256>>>(hs, Wv,   v,   BS_ROWS, NKV * HD, HID);
    sgemm_kernel<<<gBig, 256>>>(hs, Wphi, phi, BS_ROWS, NH * HD,  HID);

    // rope + kappa (in place -> Qk, Kk)
    {
        long qp = (long)B * S * NH * 32;
        rope_kappa_kernel<<<(unsigned)((qp + 255) / 256), 256>>>(q, NH, qp);
        long kp = (long)B * S * NKV * 32;
        rope_kappa_kernel<<<(unsigned)((kp + 255) / 256), 256>>>(k, NKV, kp);
    }

    qg_kernel<<<B * NH, 256>>>();
    {
        int warps = B * NH * S;                 // 262144
        logits_kernel<<<warps / 8, 256>>>();    // 8 warps per block
    }
    softmax_kernel<<<B * NH, 256>>>();
    outer_kernel<<<B * NH, 256>>>();
    attnmul_kernel<<<dim3(S / 64, B * NH), 256>>>();

    // output projection
    sgemm_kernel<<<gBig, 256>>>(ctx, Wo, out, BS_ROWS, HID, HID);
}

// round 6
// speedup vs baseline: 2.4618x; 2.4618x over previous
#include <cuda_runtime.h>
#include <math.h>
#include <cstdint>

// ---------------- problem constants ----------------
#define B 2
#define S 4096
#define HID 2048
#define NH 32
#define NKV 8
#define HD 64
#define GROUPS 4
#define BS_ROWS (B * S)     // 8192
#define GK HID              // all 5 GEMMs have K = 2048
#define KITERS (GK / 32)    // 64 k-iterations of 32 floats

// tcgen05 only exists on the arch-specific ('a') targets.
#if defined(__CUDA_ARCH_FEAT_SM103_ALL) || defined(__CUDA_ARCH_FEAT_SM100_ALL)
#define HAS_TCGEN05 1
#else
#define HAS_TCGEN05 0
#endif

// ---------------- generic ptx helpers ----------------
__device__ __forceinline__ uint32_t elect_one_pred() {
    uint32_t pred;
    asm volatile(
        "{\n\t.reg .pred p;\n\t"
        "elect.sync _|p, 0xFFFFFFFF;\n\t"
        "selp.b32 %0, 1, 0, p;\n\t}"
        : "=r"(pred));
    return pred;
}

__device__ __forceinline__ uint32_t smem_u32(const void* p) {
    uint32_t a;
    asm("{ .reg .u64 t; cvta.to.shared.u64 t, %1; cvt.u32.u64 %0, t; }" : "=r"(a) : "l"(p));
    return a;
}

// round-to-nearest tf32 truncation (exactly representable in fp32)
__device__ __forceinline__ float to_tf32(float x) {
    float r;
    asm("cvt.rna.tf32.f32 %0, %1;" : "=f"(r) : "f"(x));
    return r;
}

#define MBARRIER_INIT(addr, cnt) \
    asm volatile("mbarrier.init.shared.b64 [%0], %1;" :: "r"((uint32_t)(addr)), "r"((uint32_t)(cnt)) : "memory")

// BOUNDED wait: terminates (observably wrong) instead of hanging on protocol bugs.
__device__ __forceinline__ void mbar_wait_bounded(uint32_t mbar, uint32_t parity) {
    uint32_t done = 0;
    for (int i = 0; i < 2000000; ++i) {
        asm volatile(
            "{\n\t.reg .pred p;\n\t"
            "mbarrier.try_wait.parity.acquire.cta.shared::cta.b64 p, [%1], %2;\n\t"
            "selp.b32 %0, 1, 0, p;\n\t}"
            : "=r"(done) : "r"(mbar), "r"(parity) : "memory");
        if (done) break;
    }
}

#define SWZ(o) ((o) ^ (((o) >> 3) & 0x70))

__device__ __forceinline__ void cp_async16(uint32_t dst, const void* src) {
    asm volatile("cp.async.cg.shared.global [%0], [%1], 16;" :: "r"(dst), "l"(src));
}
#define CP_COMMIT() asm volatile("cp.async.commit_group;" ::: "memory")
#define CP_WAIT1()  asm volatile("cp.async.wait_group 1;" ::: "memory")
#define FENCE_PROXY_ASYNC_SHARED_CTA() asm volatile("fence.proxy.async.shared::cta;" ::: "memory")

// ---------------- tcgen05 helpers (guarded) ----------------
#if HAS_TCGEN05
#define TCGEN05_ALLOC(smem_result_addr, nCols) \
    asm volatile("tcgen05.alloc.cta_group::1.sync.aligned.shared::cta.b32 [%0], %1;" \
        :: "r"((uint32_t)(smem_result_addr)), "r"((uint32_t)(nCols)) : "memory")
#define TCGEN05_DEALLOC(tmem_addr, nCols) \
    asm volatile("tcgen05.dealloc.cta_group::1.sync.aligned.b32 %0, %1;" :: "r"(tmem_addr), "r"((uint32_t)(nCols)))
#define TCGEN05_RELINQUISH() \
    asm volatile("tcgen05.relinquish_alloc_permit.cta_group::1.sync.aligned;")
#define TCGEN05_COMMIT(mbar_smem_addr) \
    asm volatile("tcgen05.commit.cta_group::1.mbarrier::arrive::one.shared::cluster.b64 [%0];" \
        :: "r"((uint32_t)(mbar_smem_addr)) : "memory")
#define TCGEN05_WAIT_LD()  asm volatile("tcgen05.wait::ld.sync.aligned;" ::: "memory")
#define TCGEN05_FENCE_AFTER()  asm volatile("tcgen05.fence::after_thread_sync;" ::: "memory")
#define TCGEN05_FENCE_BEFORE() asm volatile("tcgen05.fence::before_thread_sync;" ::: "memory")

#define TCGEN05_LD_32X32B_X32(r, tmem_addr) \
    asm volatile( \
        "tcgen05.ld.sync.aligned.32x32b.x32.b32 " \
        "{%0, %1, %2, %3, %4, %5, %6, %7, " \
        " %8, %9, %10, %11, %12, %13, %14, %15, " \
        " %16, %17, %18, %19, %20, %21, %22, %23, " \
        " %24, %25, %26, %27, %28, %29, %30, %31}, [%32];" \
        : "=r"((r)[0]),  "=r"((r)[1]),  "=r"((r)[2]),  "=r"((r)[3]), \
          "=r"((r)[4]),  "=r"((r)[5]),  "=r"((r)[6]),  "=r"((r)[7]), \
          "=r"((r)[8]),  "=r"((r)[9]),  "=r"((r)[10]), "=r"((r)[11]), \
          "=r"((r)[12]), "=r"((r)[13]), "=r"((r)[14]), "=r"((r)[15]), \
          "=r"((r)[16]), "=r"((r)[17]), "=r"((r)[18]), "=r"((r)[19]), \
          "=r"((r)[20]), "=r"((r)[21]), "=r"((r)[22]), "=r"((r)[23]), \
          "=r"((r)[24]), "=r"((r)[25]), "=r"((r)[26]), "=r"((r)[27]), \
          "=r"((r)[28]), "=r"((r)[29]), "=r"((r)[30]), "=r"((r)[31]) \
        : "r"(tmem_addr))

__device__ __forceinline__ void tcgen05_mma_tf32_ss(uint32_t d, uint64_t ad, uint64_t bd,
                                                    uint32_t idesc, uint32_t en) {
    asm volatile(
        "{\n\t.reg .pred p;\n\t"
        "setp.ne.u32 p, %4, 0;\n\t"
        "tcgen05.mma.cta_group::1.kind::tf32 [%0], %1, %2, %3, p;\n\t}"
        :: "r"(d), "l"(ad), "l"(bd), "r"(idesc), "r"(en) : "memory");
}
#endif // HAS_TCGEN05

// SW128 K-major SMEM matrix descriptor
static constexpr uint64_t SMEM_DESC_BASE_SW128 =
    (uint64_t(2) << 61) | (uint64_t(1) << 46) | (uint64_t(64) << 32) | (uint64_t(1) << 16);
#define MAKE_SMEM_DESC(base_addr) (SMEM_DESC_BASE_SW128 | ((uint64_t)((base_addr) >> 4) & 0x3FFF))

// ---------------- scratch (static device globals) ----------------
__device__ float g_q  [(size_t)B * S * NH  * HD];
__device__ float g_k  [(size_t)B * S * NKV * HD];
__device__ float g_v  [(size_t)B * S * NKV * HD];
__device__ float g_phi[(size_t)B * S * NH  * HD];
__device__ float g_ctx[(size_t)B * S * NH  * HD];
__device__ float g_Qg [B * NH * HD];
__device__ float g_logits[B * NH * S];
__device__ float g_alpha [B * NH * S];
__device__ float g_M  [B * NH * HD * HD];
// hi/lo split of the GEMM A operand (hs for projections, then ctx for Wo)
__device__ float g_Ahi[(size_t)BS_ROWS * HID];
__device__ float g_Alo[(size_t)BS_ROWS * HID];
// transposed + split weights: [N, K] K-major
__device__ float g_WqT_hi  [HID * HID];
__device__ float g_WqT_lo  [HID * HID];
__device__ float g_WkT_hi  [512 * HID];
__device__ float g_WkT_lo  [512 * HID];
__device__ float g_WvT_hi  [512 * HID];
__device__ float g_WvT_lo  [512 * HID];
__device__ float g_WphiT_hi[HID * HID];
__device__ float g_WphiT_lo[HID * HID];
__device__ float g_WoT_hi  [HID * HID];
__device__ float g_WoT_lo  [HID * HID];

// ---------------- 3xTF32 tcgen05 GEMM -------------------------------------
// C[8192, N] = A[8192,2048] @ Bt[N,2048]^T with A,B split into tf32 hi+lo.
// CTA tile 128(M) x 256(N), K staged 32 floats, 2-stage cp.async pipeline, 256 threads.
#define TILE_M 128
#define TILE_N 256
#define STAGES 2
#define A_HALF (TILE_M * 128)                 // 16KB per hi or lo A tile
#define B_HALF (TILE_N * 128)                 // 32KB per hi or lo B tile
#define STAGE_BYTES (2 * A_HALF + 2 * B_HALF) // 96KB
#define SM_EMPTY(s) (8 + (s) * 8)
#define SM_DONE 48
#define SM_AHI(s) (1024 + (s) * STAGE_BYTES)
#define SM_ALO(s) (SM_AHI(s) + A_HALF)
#define SM_BHI(s) (SM_AHI(s) + 2 * A_HALF)
#define SM_BLO(s) (SM_BHI(s) + B_HALF)
#define SMEM_GEMM (1024 + STAGES * STAGE_BYTES)   // 197632 bytes

static constexpr uint32_t IDESC_TF32 =
    (1u << 4)              // D type F32
  | (2u << 7)              // A type TF32
  | (2u << 10)             // B type TF32
  | ((TILE_N / 8) << 17)   // N
  | ((TILE_M / 16) << 24); // M

__device__ __forceinline__ void load_region(uint32_t dst, const float* __restrict__ src,
                                            int rows, int row0, int k0, int tid) {
    // rows*8 16B-chunks, strided by 256 threads
    int total = rows * 8;
    for (int chunk = tid; chunk < total; chunk += 256) {
        int row = chunk >> 3, c = chunk & 7;
        uint32_t off = (uint32_t)(row * 128 + c * 16);
        cp_async16(dst + SWZ(off), src + (size_t)(row0 + row) * GK + k0 + c * 4);
    }
}

__device__ __forceinline__ void load_stage(uint32_t sb, int st,
                                           const float* __restrict__ Ahi, const float* __restrict__ Alo,
                                           const float* __restrict__ Bhi, const float* __restrict__ Blo,
                                           int m0, int n0, int k0, int tid) {
    load_region(sb + SM_AHI(st), Ahi, TILE_M, m0, k0, tid);
    load_region(sb + SM_ALO(st), Alo, TILE_M, m0, k0, tid);
    load_region(sb + SM_BHI(st), Bhi, TILE_N, n0, k0, tid);
    load_region(sb + SM_BLO(st), Blo, TILE_N, n0, k0, tid);
}

__global__ __launch_bounds__(256, 1)
void tc_gemm(const float* __restrict__ Ahi, const float* __restrict__ Alo,
             const float* __restrict__ Bhi, const float* __restrict__ Blo,
             float* __restrict__ C, int N) {
#if HAS_TCGEN05
    extern __shared__ char smem[];
    uint32_t sb = smem_u32(smem);
    const int tid = threadIdx.x;
    const int wid = tid >> 5, lid = tid & 31;
    const int m0 = blockIdx.y * TILE_M;
    const int n0 = blockIdx.x * TILE_N;

    if (tid == 0) {
        #pragma unroll
        for (int s = 0; s < STAGES; s++) MBARRIER_INIT(sb + SM_EMPTY(s), 1);
        MBARRIER_INIT(sb + SM_DONE, 1);
    }
    __syncthreads();
    if (wid == 0) {
        TCGEN05_ALLOC(sb, 256);
        TCGEN05_RELINQUISH();
    }
    __syncthreads();
    uint32_t tbase;
    asm volatile("ld.shared.b32 %0, [%1];" : "=r"(tbase) : "r"(sb));

    // prologue: fill both stages
    #pragma unroll
    for (int s = 0; s < STAGES; s++) {
        load_stage(sb, s, Ahi, Alo, Bhi, Blo, m0, n0, s * 32, tid);
        CP_COMMIT();
    }

    int st = 0, phE = 0;
    for (int kt = 0; kt < KITERS; ++kt) {
        CP_WAIT1();
        __syncthreads();                        // stage st resident
        if (wid == 0) {
            uint32_t en0 = (kt > 0) ? 1u : 0u;
            if (elect_one_pred()) {
                FENCE_PROXY_ASYNC_SHARED_CTA();
                uint64_t ahi = MAKE_SMEM_DESC(sb + SM_AHI(st));
                uint64_t alo = MAKE_SMEM_DESC(sb + SM_ALO(st));
                uint64_t bhi = MAKE_SMEM_DESC(sb + SM_BHI(st));
                uint64_t blo = MAKE_SMEM_DESC(sb + SM_BLO(st));
                #pragma unroll
                for (int s8 = 0; s8 < 4; s8++) {
                    uint64_t o = (uint64_t)(s8 * 2);
                    tcgen05_mma_tf32_ss(tbase, ahi + o, bhi + o, IDESC_TF32,
                                        (kt == 0 && s8 == 0) ? 0u : 1u);
                    tcgen05_mma_tf32_ss(tbase, ahi + o, blo + o, IDESC_TF32, 1u);
                    tcgen05_mma_tf32_ss(tbase, alo + o, bhi + o, IDESC_TF32, 1u);
                }
                TCGEN05_COMMIT(sb + SM_EMPTY(st));
            }
        }
        if (kt + STAGES < KITERS) {
            mbar_wait_bounded(sb + SM_EMPTY(st), phE);     // MMA done with this buffer
            load_stage(sb, st, Ahi, Alo, Bhi, Blo, m0, n0, (kt + STAGES) * 32, tid);
        }
        CP_COMMIT();   // unconditional: keeps group count constant
        if (++st == STAGES) { st = 0; phE ^= 1; }
    }

    if (wid == 0) {
        if (elect_one_pred()) TCGEN05_COMMIT(sb + SM_DONE);
    }
    mbar_wait_bounded(sb + SM_DONE, 0);
    TCGEN05_FENCE_AFTER();

    // epilogue: warps 0-3 read their 32-lane TMEM subpartitions
    if (wid < 4) {
        int row = m0 + wid * 32 + lid;
        float* crow = C + (size_t)row * N + n0;
        for (int c0 = 0; c0 < TILE_N; c0 += 32) {
            uint32_t r[32];
            TCGEN05_LD_32X32B_X32(r, tbase + c0);
            TCGEN05_WAIT_LD();
            #pragma unroll
            for (int j = 0; j < 32; j += 4) {
                float4 v = make_float4(__uint_as_float(r[j]),     __uint_as_float(r[j + 1]),
                                       __uint_as_float(r[j + 2]), __uint_as_float(r[j + 3]));
                *(float4*)(crow + c0 + j) = v;
            }
        }
        TCGEN05_FENCE_BEFORE();
    }
    __syncthreads();
    if (wid == 0) {
        TCGEN05_DEALLOC(tbase, 256);
    }
#else
    // Fallback for the non-'a' compile target: correct (slow) per-element GEMM.
    const int m0 = blockIdx.y * TILE_M;
    const int n0 = blockIdx.x * TILE_N;
    for (int idx = threadIdx.x; idx < TILE_M * TILE_N; idx += blockDim.x) {
        int m = m0 + idx / TILE_N;
        int n = n0 + idx % TILE_N;
        const float* ah = Ahi + (size_t)m * GK;
        const float* al = Alo + (size_t)m * GK;
        const float* bh = Bhi + (size_t)n * GK;
        const float* bl = Blo + (size_t)n * GK;
        float acc = 0.0f;
        for (int k = 0; k < GK; ++k)
            acc = fmaf(ah[k] + al[k], bh[k] + bl[k], acc);
        C[(size_t)m * N + n] = acc;
    }
#endif
}

// ---------------- split: hi = tf32(x), lo = x - hi ----------------
__global__ __launch_bounds__(256) void split_kernel(const float* __restrict__ in,
                                                    float* __restrict__ hi,
                                                    float* __restrict__ lo, long n4) {
    long i = (long)blockIdx.x * blockDim.x + threadIdx.x;
    if (i >= n4) return;
    float4 x = ((const float4*)in)[i];
    float4 h, l;
    h.x = to_tf32(x.x); l.x = x.x - h.x;
    h.y = to_tf32(x.y); l.y = x.y - h.y;
    h.z = to_tf32(x.z); l.z = x.z - h.z;
    h.w = to_tf32(x.w); l.w = x.w - h.w;
    ((float4*)hi)[i] = h;
    ((float4*)lo)[i] = l;
}

// ---------------- transpose + split: out_hi/lo[N,K] = split(in[K,N]^T) ----------------
__global__ __launch_bounds__(256) void transpose_split_kernel(const float* __restrict__ in,
                                                              float* __restrict__ out_hi,
                                                              float* __restrict__ out_lo,
                                                              int R, int Ccols) {
    __shared__ float t[32][33];
    int c0 = blockIdx.x * 32, r0 = blockIdx.y * 32;
    int x = threadIdx.x & 31, y = (threadIdx.x >> 5) * 4;
    #pragma unroll
    for (int i = 0; i < 4; i++)
        t[y + i][x] = in[(size_t)(r0 + y + i) * Ccols + c0 + x];
    __syncthreads();
    #pragma unroll
    for (int i = 0; i < 4; i++) {
        float v = t[x][y + i];
        float h = to_tf32(v);
        size_t o = (size_t)(c0 + y + i) * R + r0 + x;
        out_hi[o] = h;
        out_lo[o] = v - h;
    }
}

// ---------------- fused RoPE + kappa (elu+1), in place on [B,S,H,64] ----------------
__global__ void rope_kappa_kernel(float* __restrict__ x, int H, long total_pairs) {
    long idx = (long)blockIdx.x * blockDim.x + threadIdx.x;
    if (idx >= total_pairs) return;
    int j = (int)(idx & 31);
    long t = idx >> 5;
    int h = (int)(t % H); t /= H;
    int s = (int)(t % S);
    int b = (int)(t / S);

    float e = (float)(2 * j) / 64.0f;
    float invf = 1.0f / powf(10000.0f, e);
    float ang = (float)s * invf;
    float c, sn;
    sincosf(ang, &sn, &c);

    size_t base = (((size_t)b * S + s) * H + h) * 64;
    float x1 = x[base + j];
    float x2 = x[base + j + 32];
    float o1 = x1 * c - x2 * sn;
    float o2 = x2 * c + x1 * sn;
    o1 = (o1 > 0.0f) ? (o1 + 1.0f) : expf(o1);
    o2 = (o2 > 0.0f) ? (o2 + 1.0f) : expf(o2);
    x[base + j]      = o1;
    x[base + j + 32] = o2;
}

// ---------------- Qg = mean over S of Qk ----------------
__global__ __launch_bounds__(256) void qg_kernel() {
    int bh = blockIdx.x;
    int b = bh / NH, h = bh % NH;
    int d  = threadIdx.x % 64;
    int sg = threadIdx.x / 64;
    float sum = 0.0f;
    for (int s = sg; s < S; s += 4)
        sum += g_q[(((size_t)b * S + s) * NH + h) * 64 + d];
    __shared__ float red[256];
    red[threadIdx.x] = sum;
    __syncthreads();
    if (sg == 0) {
        float tot = red[d] + red[64 + d] + red[128 + d] + red[192 + d];
        g_Qg[bh * 64 + d] = tot / (float)S;
    }
}

// ---------------- logits ----------------
__global__ __launch_bounds__(256) void logits_kernel() {
    int warp = (blockIdx.x * blockDim.x + threadIdx.x) >> 5;
    int lane = threadIdx.x & 31;
    int s = warp % S; int t = warp / S;
    int h = t % NH;   int b = t / NH;
    int hk = h / GROUPS;
    const float* krow = &g_k[(((size_t)b * S + s) * NKV + hk) * 64];
    const float* qrow = &g_Qg[(b * NH + h) * 64];
    float sum = krow[lane] * qrow[lane] + krow[lane + 32] * qrow[lane + 32];
    #pragma unroll
    for (int off = 16; off > 0; off >>= 1)
        sum += __shfl_xor_sync(0xffffffffu, sum, off);
    if (lane == 0)
        g_logits[((size_t)b * NH + h) * S + s] = sum;
}

// ---------------- softmax * S ----------------
__global__ __launch_bounds__(256) void softmax_kernel() {
    int bh = blockIdx.x;
    const float* row = &g_logits[(size_t)bh * S];
    __shared__ float red[256];
    float m = -INFINITY;
    for (int i = threadIdx.x; i < S; i += 256) m = fmaxf(m, row[i]);
    red[threadIdx.x] = m; __syncthreads();
    for (int st = 128; st > 0; st >>= 1) {
        if (threadIdx.x < st) red[threadIdx.x] = fmaxf(red[threadIdx.x], red[threadIdx.x + st]);
        __syncthreads();
    }
    m = red[0]; __syncthreads();
    float sum = 0.0f;
    for (int i = threadIdx.x; i < S; i += 256) sum += expf(row[i] - m);
    red[threadIdx.x] = sum; __syncthreads();
    for (int st = 128; st > 0; st >>= 1) {
        if (threadIdx.x < st) red[threadIdx.x] += red[threadIdx.x + st];
        __syncthreads();
    }
    float scale = (float)S / red[0];
    for (int i = threadIdx.x; i < S; i += 256)
        g_alpha[(size_t)bh * S + i] = expf(row[i] - m) * scale;
}

// ---------------- outer_sum state ----------------
__global__ __launch_bounds__(256) void outer_kernel() {
    int bh = blockIdx.x;
    int b = bh / NH, h = bh % NH, hk = h / GROUPS;
    __shared__ float Ws[32][64];
    __shared__ float Vs[32][64];
    int f = threadIdx.x % 64;
    int g = threadIdx.x / 64;
    float acc[16];
    #pragma unroll
    for (int i = 0; i < 16; i++) acc[i] = 0.0f;

    for (int s0 = 0; s0 < S; s0 += 32) {
        __syncthreads();
        for (int i = threadIdx.x; i < 32 * 64; i += 256) {
            int s = i / 64, d = i % 64;
            size_t idx = (((size_t)b * S + s0 + s) * NKV + hk) * 64 + d;
            float a = g_alpha[((size_t)b * NH + h) * S + s0 + s];
            Ws[s][d] = a * g_k[idx];
            Vs[s][d] = g_v[idx];
        }
        __syncthreads();
        #pragma unroll 4
        for (int s = 0; s < 32; s++) {
            float vv = Vs[s][f];
            #pragma unroll
            for (int i = 0; i < 16; i++)
                acc[i] = fmaf(Ws[s][g + 4 * i], vv, acc[i]);
        }
    }
    #pragma unroll
    for (int i = 0; i < 16; i++) {
        int d = g + 4 * i;
        g_M[((size_t)bh * 64 + d) * 64 + f] = acc[i];
    }
}

// ---------------- ctx = phi * (Qk . M) ----------------
__global__ __launch_bounds__(256) void attnmul_kernel() {
    int bh = blockIdx.y;
    int b = bh / NH, h = bh % NH;
    int s0 = blockIdx.x * 64;
    __shared__ float Ms[64][64];
    __shared__ float Qs[64][64];
    for (int i = threadIdx.x; i < 64 * 64; i += 256) {
        Ms[i / 64][i % 64] = g_M[(size_t)bh * 4096 + i];
        int s = i / 64, d = i % 64;
        Qs[s][d] = g_q[(((size_t)b * S + s0 + s) * NH + h) * 64 + d];
    }
    __syncthreads();
    int f = threadIdx.x % 64;
    int sg = threadIdx.x / 64;
    for (int s = sg; s < 64; s += 4) {
        float acc = 0.0f;
        #pragma unroll
        for (int d = 0; d < 64; d++)
            acc = fmaf(Qs[s][d], Ms[d][f], acc);
        size_t idx = (((size_t)b * S + s0 + s) * NH + h) * 64 + f;
        g_ctx[idx] = g_phi[idx] * acc;
    }
}

// ---------------- host launcher ----------------
extern "C" void kernel_launch(void* const* d_in, const int* in_sizes, int n_in,
                              void* d_out, int out_size) {
    const float* hs   = (const float*)d_in[0];
    const float* Wq   = (const float*)d_in[1];
    const float* Wk   = (const float*)d_in[2];
    const float* Wv   = (const float*)d_in[3];
    const float* Wphi = (const float*)d_in[4];
    const float* Wo   = (const float*)d_in[5];
    float* out = (float*)d_out;

    float *q, *k, *v, *phi, *ctx, *Ahi, *Alo;
    float *WqTh, *WqTl, *WkTh, *WkTl, *WvTh, *WvTl, *WpTh, *WpTl, *WoTh, *WoTl;
    cudaGetSymbolAddress((void**)&q,    g_q);
    cudaGetSymbolAddress((void**)&k,    g_k);
    cudaGetSymbolAddress((void**)&v,    g_v);
    cudaGetSymbolAddress((void**)&phi,  g_phi);
    cudaGetSymbolAddress((void**)&ctx,  g_ctx);
    cudaGetSymbolAddress((void**)&Ahi,  g_Ahi);
    cudaGetSymbolAddress((void**)&Alo,  g_Alo);
    cudaGetSymbolAddress((void**)&WqTh, g_WqT_hi);
    cudaGetSymbolAddress((void**)&WqTl, g_WqT_lo);
    cudaGetSymbolAddress((void**)&WkTh, g_WkT_hi);
    cudaGetSymbolAddress((void**)&WkTl, g_WkT_lo);
    cudaGetSymbolAddress((void**)&WvTh, g_WvT_hi);
    cudaGetSymbolAddress((void**)&WvTl, g_WvT_lo);
    cudaGetSymbolAddress((void**)&WpTh, g_WphiT_hi);
    cudaGetSymbolAddress((void**)&WpTl, g_WphiT_lo);
    cudaGetSymbolAddress((void**)&WoTh, g_WoT_hi);
    cudaGetSymbolAddress((void**)&WoTl, g_WoT_lo);

    cudaFuncSetAttribute(tc_gemm, cudaFuncAttributeMaxDynamicSharedMemorySize, SMEM_GEMM);

    // transpose + split all weights to hi/lo [N, K]
    transpose_split_kernel<<<dim3(HID / 32, HID / 32), 256>>>(Wq,   WqTh, WqTl, HID, HID);
    transpose_split_kernel<<<dim3(512 / 32, HID / 32), 256>>>(Wk,   WkTh, WkTl, HID, 512);
    transpose_split_kernel<<<dim3(512 / 32, HID / 32), 256>>>(Wv,   WvTh, WvTl, HID, 512);
    transpose_split_kernel<<<dim3(HID / 32, HID / 32), 256>>>(Wphi, WpTh, WpTl, HID, HID);
    transpose_split_kernel<<<dim3(HID / 32, HID / 32), 256>>>(Wo,   WoTh, WoTl, HID, HID);

    // split hidden_states -> Ahi/Alo
    {
        long n4 = (long)BS_ROWS * HID / 4;
        split_kernel<<<(unsigned)((n4 + 255) / 256), 256>>>(hs, Ahi, Alo, n4);
    }

    // projections (3xTF32 tcgen05)
    dim3 gBig(HID / TILE_N, BS_ROWS / TILE_M);   // (8, 64)
    dim3 gKV (512 / TILE_N, BS_ROWS / TILE_M);   // (2, 64)
    tc_gemm<<<gBig, 256, SMEM_GEMM>>>(Ahi, Alo, WqTh, WqTl, q,   HID);
    tc_gemm<<<gKV,  256, SMEM_GEMM>>>(Ahi, Alo, WkTh, WkTl, k,   512);
    tc_gemm<<<gKV,  256, SMEM_GEMM>>>(Ahi, Alo, WvTh, WvTl, v,   512);
    tc_gemm<<<gBig, 256, SMEM_GEMM>>>(Ahi, Alo, WpTh, WpTl, phi, HID);

    // rope + kappa
    {
        long qp = (long)B * S * NH * 32;
        rope_kappa_kernel<<<(unsigned)((qp + 255) / 256), 256>>>(q, NH, qp);
        long kp = (long)B * S * NKV * 32;
        rope_kappa_kernel<<<(unsigned)((kp + 255) / 256), 256>>>(k, NKV, kp);
    }

    qg_kernel<<<B * NH, 256>>>();
    logits_kernel<<<(B * NH * S) / 8, 256>>>();
    softmax_kernel<<<B * NH, 256>>>();
    outer_kernel<<<B * NH, 256>>>();
    attnmul_kernel<<<dim3(S / 64, B * NH), 256>>>();

    // split ctx -> Ahi/Alo (projection GEMMs are done with hs by now)
    {
        long n4 = (long)BS_ROWS * HID / 4;
        split_kernel<<<(unsigned)((n4 + 255) / 256), 256>>>(ctx, Ahi, Alo, n4);
    }

    // output projection
    tc_gemm<<<gBig, 256, SMEM_GEMM>>>(Ahi, Alo, WoTh, WoTl, out, HID);
}

// round 7
// speedup vs baseline: 4.7244x; 1.9191x over previous
#include <cuda_runtime.h>
#include <math.h>
#include <cstdint>

// ---------------- problem constants ----------------
#define B 2
#define S 4096
#define HID 2048
#define NH 32
#define NKV 8
#define HD 64
#define GROUPS 4
#define BS_ROWS (B * S)     // 8192
#define GK HID              // all 5 GEMMs have K = 2048
#define KITERS (GK / 32)    // 64 k-iterations of 32 floats

#if defined(__CUDA_ARCH_FEAT_SM103_ALL) || defined(__CUDA_ARCH_FEAT_SM100_ALL)
#define HAS_TCGEN05 1
#else
#define HAS_TCGEN05 0
#endif

// ---------------- generic ptx helpers ----------------
__device__ __forceinline__ uint32_t elect_one_pred() {
    uint32_t pred;
    asm volatile(
        "{\n\t.reg .pred p;\n\t"
        "elect.sync _|p, 0xFFFFFFFF;\n\t"
        "selp.b32 %0, 1, 0, p;\n\t}"
        : "=r"(pred));
    return pred;
}

__device__ __forceinline__ uint32_t smem_u32(const void* p) {
    uint32_t a;
    asm("{ .reg .u64 t; cvta.to.shared.u64 t, %1; cvt.u32.u64 %0, t; }" : "=r"(a) : "l"(p));
    return a;
}

__device__ __forceinline__ uint32_t cluster_rank() {
    uint32_t r;
    asm("mov.u32 %0, %%cluster_ctarank;" : "=r"(r));
    return r;
}

__device__ __forceinline__ float to_tf32(float x) {
    float r;
    asm("cvt.rna.tf32.f32 %0, %1;" : "=f"(r) : "f"(x));
    return r;
}

#define MBARRIER_INIT(addr, cnt) \
    asm volatile("mbarrier.init.shared.b64 [%0], %1;" :: "r"((uint32_t)(addr)), "r"((uint32_t)(cnt)) : "memory")
#define MBARRIER_INVAL(addr) \
    asm volatile("mbarrier.inval.shared.b64 [%0];" :: "r"((uint32_t)(addr)) : "memory")

// arrive on rank0's instance of this barrier (release, cluster scope)
#define MBARRIER_ARRIVE_RANK0(local_addr) \
    asm volatile( \
        "{\n\t.reg .b32 remAddr;\n\t" \
        "mapa.shared::cluster.u32 remAddr, %0, 0;\n\t" \
        "mbarrier.arrive.shared::cluster.b64 _, [remAddr];\n\t}" \
        :: "r"((uint32_t)(local_addr)) : "memory")

// BOUNDED wait: terminates (observably wrong) instead of hanging on protocol bugs.
__device__ __forceinline__ void mbar_wait_bounded(uint32_t mbar, uint32_t parity) {
    uint32_t done = 0;
    for (int i = 0; i < 4000000; ++i) {
        asm volatile(
            "{\n\t.reg .pred p;\n\t"
            "mbarrier.try_wait.parity.acquire.cta.shared::cta.b64 p, [%1], %2;\n\t"
            "selp.b32 %0, 1, 0, p;\n\t}"
            : "=r"(done) : "r"(mbar), "r"(parity) : "memory");
        if (done) break;
    }
}

#define SWZ(o) ((o) ^ (((o) >> 3) & 0x70))

__device__ __forceinline__ void cp_async16(uint32_t dst, const void* src) {
    asm volatile("cp.async.cg.shared.global [%0], [%1], 16;" :: "r"(dst), "l"(src));
}
#define CP_COMMIT() asm volatile("cp.async.commit_group;" ::: "memory")
#define CP_WAIT1()  asm volatile("cp.async.wait_group 1;" ::: "memory")
#define FENCE_PROXY_ASYNC_SHARED_CTA() asm volatile("fence.proxy.async.shared::cta;" ::: "memory")
#define CLUSTER_SYNC() do { \
    asm volatile("barrier.cluster.arrive.aligned;" ::: "memory"); \
    asm volatile("barrier.cluster.wait.aligned;" ::: "memory"); \
} while (0)

// ---------------- tcgen05 helpers (guarded, cta_group::2) ----------------
#if HAS_TCGEN05
#define TCGEN05_ALLOC_CG2(smem_result_addr, nCols) \
    asm volatile("tcgen05.alloc.cta_group::2.sync.aligned.shared::cta.b32 [%0], %1;" \
        :: "r"((uint32_t)(smem_result_addr)), "r"((uint32_t)(nCols)) : "memory")
#define TCGEN05_DEALLOC_CG2(tmem_addr, nCols) \
    asm volatile("tcgen05.dealloc.cta_group::2.sync.aligned.b32 %0, %1;" :: "r"(tmem_addr), "r"((uint32_t)(nCols)))
#define TCGEN05_RELINQUISH_CG2() \
    asm volatile("tcgen05.relinquish_alloc_permit.cta_group::2.sync.aligned;")
#define TCGEN05_COMMIT_MC_CG2(mbar_smem_addr, mask) \
    asm volatile("tcgen05.commit.cta_group::2.mbarrier::arrive::one.shared::cluster.multicast::cluster.b64 [%0], %1;" \
        :: "r"((uint32_t)(mbar_smem_addr)), "h"((uint16_t)(mask)) : "memory")
#define TCGEN05_WAIT_LD()  asm volatile("tcgen05.wait::ld.sync.aligned;" ::: "memory")
#define TCGEN05_FENCE_AFTER()  asm volatile("tcgen05.fence::after_thread_sync;" ::: "memory")
#define TCGEN05_FENCE_BEFORE() asm volatile("tcgen05.fence::before_thread_sync;" ::: "memory")

#define TCGEN05_LD_32X32B_X32(r, tmem_addr) \
    asm volatile( \
        "tcgen05.ld.sync.aligned.32x32b.x32.b32 " \
        "{%0, %1, %2, %3, %4, %5, %6, %7, " \
        " %8, %9, %10, %11, %12, %13, %14, %15, " \
        " %16, %17, %18, %19, %20, %21, %22, %23, " \
        " %24, %25, %26, %27, %28, %29, %30, %31}, [%32];" \
        : "=r"((r)[0]),  "=r"((r)[1]),  "=r"((r)[2]),  "=r"((r)[3]), \
          "=r"((r)[4]),  "=r"((r)[5]),  "=r"((r)[6]),  "=r"((r)[7]), \
          "=r"((r)[8]),  "=r"((r)[9]),  "=r"((r)[10]), "=r"((r)[11]), \
          "=r"((r)[12]), "=r"((r)[13]), "=r"((r)[14]), "=r"((r)[15]), \
          "=r"((r)[16]), "=r"((r)[17]), "=r"((r)[18]), "=r"((r)[19]), \
          "=r"((r)[20]), "=r"((r)[21]), "=r"((r)[22]), "=r"((r)[23]), \
          "=r"((r)[24]), "=r"((r)[25]), "=r"((r)[26]), "=r"((r)[27]), \
          "=r"((r)[28]), "=r"((r)[29]), "=r"((r)[30]), "=r"((r)[31]) \
        : "r"(tmem_addr))

// tf32 cg2 SS MMA with disable-output-lane vector (8 regs, all 0)
__device__ __forceinline__ void tcgen05_mma_tf32_cg2(uint32_t d, uint64_t ad, uint64_t bd,
                                                     uint32_t idesc, uint32_t en) {
    asm volatile(
        "{\n\t.reg .pred p;\n\t"
        "setp.ne.u32 p, %5, 0;\n\t"
        "tcgen05.mma.cta_group::2.kind::tf32 [%0], %1, %2, %3, "
        "{%4, %4, %4, %4, %4, %4, %4, %4}, p;\n\t}"
        :: "r"(d), "l"(ad), "l"(bd), "r"(idesc), "r"(0u), "r"(en) : "memory");
}
#endif // HAS_TCGEN05

static constexpr uint64_t SMEM_DESC_BASE_SW128 =
    (uint64_t(2) << 61) | (uint64_t(1) << 46) | (uint64_t(64) << 32) | (uint64_t(1) << 16);
#define MAKE_SMEM_DESC(base_addr) (SMEM_DESC_BASE_SW128 | ((uint64_t)((base_addr) >> 4) & 0x3FFF))

// ---------------- scratch (static device globals) ----------------
__device__ float g_q  [(size_t)B * S * NH  * HD];
__device__ float g_k  [(size_t)B * S * NKV * HD];
__device__ float g_v  [(size_t)B * S * NKV * HD];
__device__ float g_phi[(size_t)B * S * NH  * HD];
__device__ float g_ctx[(size_t)B * S * NH  * HD];
__device__ float g_Qg [B * NH * HD];
__device__ float g_logits[B * NH * S];
__device__ float g_alpha [B * NH * S];
__device__ float g_M  [B * NH * HD * HD];
__device__ float g_Ahi[(size_t)BS_ROWS * HID];
__device__ float g_Alo[(size_t)BS_ROWS * HID];
__device__ float g_WqT_hi  [HID * HID];
__device__ float g_WqT_lo  [HID * HID];
__device__ float g_WkT_hi  [512 * HID];
__device__ float g_WkT_lo  [512 * HID];
__device__ float g_WvT_hi  [512 * HID];
__device__ float g_WvT_lo  [512 * HID];
__device__ float g_WphiT_hi[HID * HID];
__device__ float g_WphiT_lo[HID * HID];
__device__ float g_WoT_hi  [HID * HID];
__device__ float g_WoT_lo  [HID * HID];

// ---------------- cg2 3xTF32 GEMM --------------------------------------------
// Pair tile: M=256 (128 A-rows per CTA), N=256 (128 B-rows per CTA, split).
// K staged 32 floats, 3-stage cp.async ring, look-ahead 2. 256 threads/CTA.
#define ROWS_CTA 128
#define PAIR_M 256
#define PAIR_N 256
#define STAGES 3
#define REGION_BYTES (ROWS_CTA * 128)         // 16KB (one of A/B hi/lo)
#define STAGE_BYTES (4 * REGION_BYTES)        // 64KB
#define SM_FULL(s)  (8  + (s) * 8)            // rank1->rank0 readiness
#define SM_EMPTY(s) (32 + (s) * 8)            // MMA-done (multicast)
#define SM_DONE 56
#define SM_AHI(s) (1024 + (s) * STAGE_BYTES)
#define SM_ALO(s) (SM_AHI(s) + REGION_BYTES)
#define SM_BHI(s) (SM_AHI(s) + 2 * REGION_BYTES)
#define SM_BLO(s) (SM_AHI(s) + 3 * REGION_BYTES)
#define SMEM_GEMM (1024 + STAGES * STAGE_BYTES)   // 197632 bytes

static constexpr uint32_t IDESC_CG2 =
    (1u << 4)              // D type F32
  | (2u << 7)              // A type TF32
  | (2u << 10)             // B type TF32
  | ((PAIR_N / 8) << 17)   // N = 256
  | ((PAIR_M / 16) << 24); // M = 256

__device__ __forceinline__ void load_region(uint32_t dst, const float* __restrict__ src,
                                            int row0, int k0, int tid) {
    #pragma unroll
    for (int i = 0; i < 4; i++) {                 // 128 rows x 8 chunks = 1024
        int chunk = i * 256 + tid;
        int row = chunk >> 3, c = chunk & 7;
        uint32_t off = (uint32_t)(row * 128 + c * 16);
        cp_async16(dst + SWZ(off), src + (size_t)(row0 + row) * GK + k0 + c * 4);
    }
}

__device__ __forceinline__ void load_stage(uint32_t sb, int st,
                                           const float* __restrict__ Ahi, const float* __restrict__ Alo,
                                           const float* __restrict__ Bhi, const float* __restrict__ Blo,
                                           int aRow0, int bRow0, int k0, int tid) {
    load_region(sb + SM_AHI(st), Ahi, aRow0, k0, tid);
    load_region(sb + SM_ALO(st), Alo, aRow0, k0, tid);
    load_region(sb + SM_BHI(st), Bhi, bRow0, k0, tid);
    load_region(sb + SM_BLO(st), Blo, bRow0, k0, tid);
}

__global__ __launch_bounds__(256, 1) __cluster_dims__(2, 1, 1)
void tc_gemm(const float* __restrict__ Ahi, const float* __restrict__ Alo,
             const float* __restrict__ Bhi, const float* __restrict__ Blo,
             float* __restrict__ C, int N) {
    const uint32_t rank = cluster_rank();
    const int m0 = blockIdx.z * PAIR_M;
    const int n0 = blockIdx.y * PAIR_N;
#if HAS_TCGEN05
    extern __shared__ char smem[];
    uint32_t sb = smem_u32(smem);
    const int tid = threadIdx.x;
    const int wid = tid >> 5, lid = tid & 31;
    const int aRow0 = m0 + (int)rank * ROWS_CTA;
    const int bRow0 = n0 + (int)rank * ROWS_CTA;

    if (tid == 0) {
        #pragma unroll
        for (int s = 0; s < STAGES; s++) {
            MBARRIER_INIT(sb + SM_FULL(s), 1);
            MBARRIER_INIT(sb + SM_EMPTY(s), 1);
        }
        MBARRIER_INIT(sb + SM_DONE, 1);
    }
    __syncthreads();
    if (wid == 0) TCGEN05_ALLOC_CG2(sb, 256);
    __syncthreads();
    uint32_t tbase;
    asm volatile("ld.shared.b32 %0, [%1];" : "=r"(tbase) : "r"(sb));

    // prologue: load stages 0 and 1 (look-ahead 2)
    load_stage(sb, 0, Ahi, Alo, Bhi, Blo, aRow0, bRow0, 0, tid);
    CP_COMMIT();
    load_stage(sb, 1, Ahi, Alo, Bhi, Blo, aRow0, bRow0, 32, tid);
    CP_COMMIT();

    // barriers visible cluster-wide before any cross-CTA arrive/commit
    CLUSTER_SYNC();

    for (int kt = 0; kt < KITERS; ++kt) {
        const int st = kt % STAGES;
        CP_WAIT1();                 // my load(kt) landed
        __syncthreads();            // all threads' groups drained

        if (rank == 1) {
            if (wid == 0 && elect_one_pred()) {
                FENCE_PROXY_ASYNC_SHARED_CTA();
                MBARRIER_ARRIVE_RANK0(sb + SM_FULL(st));   // my tile st is ready
            }
        } else {
            if (wid == 0) {
                mbar_wait_bounded(sb + SM_FULL(st), (uint32_t)((kt / 3) & 1));
                if (elect_one_pred()) {
                    FENCE_PROXY_ASYNC_SHARED_CTA();
                    uint64_t ahi = MAKE_SMEM_DESC(sb + SM_AHI(st));
                    uint64_t alo = MAKE_SMEM_DESC(sb + SM_ALO(st));
                    uint64_t bhi = MAKE_SMEM_DESC(sb + SM_BHI(st));
                    uint64_t blo = MAKE_SMEM_DESC(sb + SM_BLO(st));
                    #pragma unroll
                    for (int s8 = 0; s8 < 4; s8++) {
                        uint64_t o = (uint64_t)(s8 * 2);
                        tcgen05_mma_tf32_cg2(tbase, ahi + o, bhi + o, IDESC_CG2,
                                             (kt == 0 && s8 == 0) ? 0u : 1u);
                        tcgen05_mma_tf32_cg2(tbase, ahi + o, blo + o, IDESC_CG2, 1u);
                        tcgen05_mma_tf32_cg2(tbase, alo + o, bhi + o, IDESC_CG2, 1u);
                    }
                    TCGEN05_COMMIT_MC_CG2(sb + SM_EMPTY(st), 0x3);
                }
            }
        }

        // refill: buffer (kt+2)%3 was read by MMA(kt-1) -> wait its EMPTY commit
        if (kt + 2 < KITERS) {
            int ld = (kt + 2) % STAGES;
            if (kt >= 1)
                mbar_wait_bounded(sb + SM_EMPTY(ld), (uint32_t)(((kt - 1) / 3) & 1));
            load_stage(sb, ld, Ahi, Alo, Bhi, Blo, aRow0, bRow0, (kt + 2) * 32, tid);
        }
        CP_COMMIT();   // unconditional: keeps group count constant
    }

    if (rank == 0 && wid == 0) {
        if (elect_one_pred()) TCGEN05_COMMIT_MC_CG2(sb + SM_DONE, 0x3);
    }
    mbar_wait_bounded(sb + SM_DONE, 0);
    TCGEN05_FENCE_AFTER();

    // epilogue: warps 0-3 read 128 lanes x 256 cols from this CTA's TMEM
    if (wid < 4) {
        int row = m0 + (int)rank * ROWS_CTA + wid * 32 + lid;
        float* crow = C + (size_t)row * N + n0;
        for (int c0 = 0; c0 < PAIR_N; c0 += 32) {
            uint32_t r[32];
            TCGEN05_LD_32X32B_X32(r, tbase + c0);
            TCGEN05_WAIT_LD();
            #pragma unroll
            for (int j = 0; j < 32; j += 4) {
                float4 v = make_float4(__uint_as_float(r[j]),     __uint_as_float(r[j + 1]),
                                       __uint_as_float(r[j + 2]), __uint_as_float(r[j + 3]));
                *(float4*)(crow + c0 + j) = v;
            }
        }
        TCGEN05_FENCE_BEFORE();
    }
    __syncthreads();
    if (tid == 0) {
        #pragma unroll
        for (int s = 0; s < STAGES; s++) {
            MBARRIER_INVAL(sb + SM_FULL(s));
            MBARRIER_INVAL(sb + SM_EMPTY(s));
        }
        MBARRIER_INVAL(sb + SM_DONE);
    }
    __syncthreads();
    if (wid == 0) {
        TCGEN05_RELINQUISH_CG2();
        TCGEN05_DEALLOC_CG2(tbase, 256);
    }
    CLUSTER_SYNC();
#else
    // Fallback for the non-'a' target: correct (slow) per-element GEMM.
    for (int idx = threadIdx.x; idx < ROWS_CTA * PAIR_N; idx += blockDim.x) {
        int m = m0 + (int)rank * ROWS_CTA + idx / PAIR_N;
        int n = n0 + idx % PAIR_N;
        const float* ah = Ahi + (size_t)m * GK;
        const float* al = Alo + (size_t)m * GK;
        const float* bh = Bhi + (size_t)n * GK;
        const float* bl = Blo + (size_t)n * GK;
        float acc = 0.0f;
        for (int k = 0; k < GK; ++k)
            acc = fmaf(ah[k] + al[k], bh[k] + bl[k], acc);
        C[(size_t)m * N + n] = acc;
    }
#endif
}

// ---------------- split: hi = tf32(x), lo = x - hi ----------------
__global__ __launch_bounds__(256) void split_kernel(const float* __restrict__ in,
                                                    float* __restrict__ hi,
                                                    float* __restrict__ lo, long n4) {
    long i = (long)blockIdx.x * blockDim.x + threadIdx.x;
    if (i >= n4) return;
    float4 x = ((const float4*)in)[i];
    float4 h, l;
    h.x = to_tf32(x.x); l.x = x.x - h.x;
    h.y = to_tf32(x.y); l.y = x.y - h.y;
    h.z = to_tf32(x.z); l.z = x.z - h.z;
    h.w = to_tf32(x.w); l.w = x.w - h.w;
    ((float4*)hi)[i] = h;
    ((float4*)lo)[i] = l;
}

// ---------------- transpose + split ----------------
__global__ __launch_bounds__(256) void transpose_split_kernel(const float* __restrict__ in,
                                                              float* __restrict__ out_hi,
                                                              float* __restrict__ out_lo,
                                                              int R, int Ccols) {
    __shared__ float t[32][33];
    int c0 = blockIdx.x * 32, r0 = blockIdx.y * 32;
    int x = threadIdx.x & 31, y = (threadIdx.x >> 5) * 4;
    #pragma unroll
    for (int i = 0; i < 4; i++)
        t[y + i][x] = in[(size_t)(r0 + y + i) * Ccols + c0 + x];
    __syncthreads();
    #pragma unroll
    for (int i = 0; i < 4; i++) {
        float v = t[x][y + i];
        float h = to_tf32(v);
        size_t o = (size_t)(c0 + y + i) * R + r0 + x;
        out_hi[o] = h;
        out_lo[o] = v - h;
    }
}

// ---------------- fused RoPE + kappa ----------------
__global__ void rope_kappa_kernel(float* __restrict__ x, int H, long total_pairs) {
    long idx = (long)blockIdx.x * blockDim.x + threadIdx.x;
    if (idx >= total_pairs) return;
    int j = (int)(idx & 31);
    long t = idx >> 5;
    int h = (int)(t % H); t /= H;
    int s = (int)(t % S);
    int b = (int)(t / S);

    float e = (float)(2 * j) / 64.0f;
    float invf = 1.0f / powf(10000.0f, e);
    float ang = (float)s * invf;
    float c, sn;
    sincosf(ang, &sn, &c);

    size_t base = (((size_t)b * S + s) * H + h) * 64;
    float x1 = x[base + j];
    float x2 = x[base + j + 32];
    float o1 = x1 * c - x2 * sn;
    float o2 = x2 * c + x1 * sn;
    o1 = (o1 > 0.0f) ? (o1 + 1.0f) : expf(o1);
    o2 = (o2 > 0.0f) ? (o2 + 1.0f) : expf(o2);
    x[base + j]      = o1;
    x[base + j + 32] = o2;
}

// ---------------- Qg = mean over S of Qk ----------------
__global__ __launch_bounds__(256) void qg_kernel() {
    int bh = blockIdx.x;
    int b = bh / NH, h = bh % NH;
    int d  = threadIdx.x % 64;
    int sg = threadIdx.x / 64;
    float sum = 0.0f;
    for (int s = sg; s < S; s += 4)
        sum += g_q[(((size_t)b * S + s) * NH + h) * 64 + d];
    __shared__ float red[256];
    red[threadIdx.x] = sum;
    __syncthreads();
    if (sg == 0) {
        float tot = red[d] + red[64 + d] + red[128 + d] + red[192 + d];
        g_Qg[bh * 64 + d] = tot / (float)S;
    }
}

// ---------------- logits ----------------
__global__ __launch_bounds__(256) void logits_kernel() {
    int warp = (blockIdx.x * blockDim.x + threadIdx.x) >> 5;
    int lane = threadIdx.x & 31;
    int s = warp % S; int t = warp / S;
    int h = t % NH;   int b = t / NH;
    int hk = h / GROUPS;
    const float* krow = &g_k[(((size_t)b * S + s) * NKV + hk) * 64];
    const float* qrow = &g_Qg[(b * NH + h) * 64];
    float sum = krow[lane] * qrow[lane] + krow[lane + 32] * qrow[lane + 32];
    #pragma unroll
    for (int off = 16; off > 0; off >>= 1)
        sum += __shfl_xor_sync(0xffffffffu, sum, off);
    if (lane == 0)
        g_logits[((size_t)b * NH + h) * S + s] = sum;
}

// ---------------- softmax * S ----------------
__global__ __launch_bounds__(256) void softmax_kernel() {
    int bh = blockIdx.x;
    const float* row = &g_logits[(size_t)bh * S];
    __shared__ float red[256];
    float m = -INFINITY;
    for (int i = threadIdx.x; i < S; i += 256) m = fmaxf(m, row[i]);
    red[threadIdx.x] = m; __syncthreads();
    for (int st = 128; st > 0; st >>= 1) {
        if (threadIdx.x < st) red[threadIdx.x] = fmaxf(red[threadIdx.x], red[threadIdx.x + st]);
        __syncthreads();
    }
    m = red[0]; __syncthreads();
    float sum = 0.0f;
    for (int i = threadIdx.x; i < S; i += 256) sum += expf(row[i] - m);
    red[threadIdx.x] = sum; __syncthreads();
    for (int st = 128; st > 0; st >>= 1) {
        if (threadIdx.x < st) red[threadIdx.x] += red[threadIdx.x + st];
        __syncthreads();
    }
    float scale = (float)S / red[0];
    for (int i = threadIdx.x; i < S; i += 256)
        g_alpha[(size_t)bh * S + i] = expf(row[i] - m) * scale;
}

// ---------------- zero g_M ----------------
__global__ __launch_bounds__(256) void zeroM_kernel() {
    int i = blockIdx.x * 256 + threadIdx.x;
    ((float4*)g_M)[i] = make_float4(0.f, 0.f, 0.f, 0.f);
}

// ---------------- outer_sum state (split over S, atomic accumulate) ----------------
#define SCHUNK 8
__global__ __launch_bounds__(256) void outer_kernel() {
    int bh = blockIdx.x;
    int sc = blockIdx.y;
    int b = bh / NH, h = bh % NH, hk = h / GROUPS;
    __shared__ float Ws[32][64];
    __shared__ float Vs[32][64];
    int f = threadIdx.x % 64;
    int g = threadIdx.x / 64;
    float acc[16];
    #pragma unroll
    for (int i = 0; i < 16; i++) acc[i] = 0.0f;

    int sBeg = sc * (S / SCHUNK), sEnd = sBeg + (S / SCHUNK);
    for (int s0 = sBeg; s0 < sEnd; s0 += 32) {
        __syncthreads();
        for (int i = threadIdx.x; i < 32 * 64; i += 256) {
            int s = i / 64, d = i % 64;
            size_t idx = (((size_t)b * S + s0 + s) * NKV + hk) * 64 + d;
            float a = g_alpha[((size_t)b * NH + h) * S + s0 + s];
            Ws[s][d] = a * g_k[idx];
            Vs[s][d] = g_v[idx];
        }
        __syncthreads();
        #pragma unroll 4
        for (int s = 0; s < 32; s++) {
            float vv = Vs[s][f];
            #pragma unroll
            for (int i = 0; i < 16; i++)
                acc[i] = fmaf(Ws[s][g + 4 * i], vv, acc[i]);
        }
    }
    #pragma unroll
    for (int i = 0; i < 16; i++) {
        int d = g + 4 * i;
        atomicAdd(&g_M[((size_t)bh * 64 + d) * 64 + f], acc[i]);
    }
}

// ---------------- ctx = phi * (Qk . M) ----------------
__global__ __launch_bounds__(256) void attnmul_kernel() {
    int bh = blockIdx.y;
    int b = bh / NH, h = bh % NH;
    int s0 = blockIdx.x * 64;
    __shared__ float Ms[64][64];
    __shared__ float Qs[64][64];
    for (int i = threadIdx.x; i < 64 * 64; i += 256) {
        Ms[i / 64][i % 64] = g_M[(size_t)bh * 4096 + i];
        int s = i / 64, d = i % 64;
        Qs[s][d] = g_q[(((size_t)b * S + s0 + s) * NH + h) * 64 + d];
    }
    __syncthreads();
    int f = threadIdx.x % 64;
    int sg = threadIdx.x / 64;
    for (int s = sg; s < 64; s += 4) {
        float acc = 0.0f;
        #pragma unroll
        for (int d = 0; d < 64; d++)
            acc = fmaf(Qs[s][d], Ms[d][f], acc);
        size_t idx = (((size_t)b * S + s0 + s) * NH + h) * 64 + f;
        g_ctx[idx] = g_phi[idx] * acc;
    }
}

// ---------------- host launcher ----------------
extern "C" void kernel_launch(void* const* d_in, const int* in_sizes, int n_in,
                              void* d_out, int out_size) {
    const float* hs   = (const float*)d_in[0];
    const float* Wq   = (const float*)d_in[1];
    const float* Wk   = (const float*)d_in[2];
    const float* Wv   = (const float*)d_in[3];
    const float* Wphi = (const float*)d_in[4];
    const float* Wo   = (const float*)d_in[5];
    float* out = (float*)d_out;

    float *q, *k, *v, *phi, *ctx, *Ahi, *Alo;
    float *WqTh, *WqTl, *WkTh, *WkTl, *WvTh, *WvTl, *WpTh, *WpTl, *WoTh, *WoTl;
    cudaGetSymbolAddress((void**)&q,    g_q);
    cudaGetSymbolAddress((void**)&k,    g_k);
    cudaGetSymbolAddress((void**)&v,    g_v);
    cudaGetSymbolAddress((void**)&phi,  g_phi);
    cudaGetSymbolAddress((void**)&ctx,  g_ctx);
    cudaGetSymbolAddress((void**)&Ahi,  g_Ahi);
    cudaGetSymbolAddress((void**)&Alo,  g_Alo);
    cudaGetSymbolAddress((void**)&WqTh, g_WqT_hi);
    cudaGetSymbolAddress((void**)&WqTl, g_WqT_lo);
    cudaGetSymbolAddress((void**)&WkTh, g_WkT_hi);
    cudaGetSymbolAddress((void**)&WkTl, g_WkT_lo);
    cudaGetSymbolAddress((void**)&WvTh, g_WvT_hi);
    cudaGetSymbolAddress((void**)&WvTl, g_WvT_lo);
    cudaGetSymbolAddress((void**)&WpTh, g_WphiT_hi);
    cudaGetSymbolAddress((void**)&WpTl, g_WphiT_lo);
    cudaGetSymbolAddress((void**)&WoTh, g_WoT_hi);
    cudaGetSymbolAddress((void**)&WoTl, g_WoT_lo);

    cudaFuncSetAttribute(tc_gemm, cudaFuncAttributeMaxDynamicSharedMemorySize, SMEM_GEMM);

    // transpose + split all weights to hi/lo [N, K]
    transpose_split_kernel<<<dim3(HID / 32, HID / 32), 256>>>(Wq,   WqTh, WqTl, HID, HID);
    transpose_split_kernel<<<dim3(512 / 32, HID / 32), 256>>>(Wk,   WkTh, WkTl, HID, 512);
    transpose_split_kernel<<<dim3(512 / 32, HID / 32), 256>>>(Wv,   WvTh, WvTl, HID, 512);
    transpose_split_kernel<<<dim3(HID / 32, HID / 32), 256>>>(Wphi, WpTh, WpTl, HID, HID);
    transpose_split_kernel<<<dim3(HID / 32, HID / 32), 256>>>(Wo,   WoTh, WoTl, HID, HID);

    // split hidden_states -> Ahi/Alo
    {
        long n4 = (long)BS_ROWS * HID / 4;
        split_kernel<<<(unsigned)((n4 + 255) / 256), 256>>>(hs, Ahi, Alo, n4);
    }

    // projections: cluster pairs — grid (2, N/256, M/256)
    dim3 gBig(2, HID / PAIR_N, BS_ROWS / PAIR_M);   // (2, 8, 32)
    dim3 gKV (2, 512 / PAIR_N, BS_ROWS / PAIR_M);   // (2, 2, 32)
    tc_gemm<<<gBig, 256, SMEM_GEMM>>>(Ahi, Alo, WqTh, WqTl, q,   HID);
    tc_gemm<<<gKV,  256, SMEM_GEMM>>>(Ahi, Alo, WkTh, WkTl, k,   512);
    tc_gemm<<<gKV,  256, SMEM_GEMM>>>(Ahi, Alo, WvTh, WvTl, v,   512);
    tc_gemm<<<gBig, 256, SMEM_GEMM>>>(Ahi, Alo, WpTh, WpTl, phi, HID);

    // rope + kappa
    {
        long qp = (long)B * S * NH * 32;
        rope_kappa_kernel<<<(unsigned)((qp + 255) / 256), 256>>>(q, NH, qp);
        long kp = (long)B * S * NKV * 32;
        rope_kappa_kernel<<<(unsigned)((kp + 255) / 256), 256>>>(k, NKV, kp);
    }

    qg_kernel<<<B * NH, 256>>>();
    logits_kernel<<<(B * NH * S) / 8, 256>>>();
    softmax_kernel<<<B * NH, 256>>>();
    zeroM_kernel<<<(B * NH * HD * HD) / 1024, 256>>>();
    outer_kernel<<<dim3(B * NH, SCHUNK), 256>>>();
    attnmul_kernel<<<dim3(S / 64, B * NH), 256>>>();

    // split ctx -> Ahi/Alo (projection GEMMs done with hs by now)
    {
        long n4 = (long)BS_ROWS * HID / 4;
        split_kernel<<<(unsigned)((n4 + 255) / 256), 256>>>(ctx, Ahi, Alo, n4);
    }

    // output projection
    tc_gemm<<<gBig, 256, SMEM_GEMM>>>(Ahi, Alo, WoTh, WoTl, out, HID);
}

// round 10
// speedup vs baseline: 6.4795x; 1.3715x over previous
#include <cuda_runtime.h>
#include <cuda_bf16.h>
#include <math.h>
#include <cstdint>

// ---------------- problem constants ----------------
#define B 2
#define S 4096
#define HID 2048
#define NH 32
#define NKV 8
#define HD 64
#define GROUPS 4
#define BS_ROWS (B * S)     // 8192
#define GK HID              // all 5 GEMMs have K = 2048
#define KITERS (GK / 64)    // 32 k-iterations of 64 bf16 elements

#if defined(__CUDA_ARCH_FEAT_SM103_ALL) || defined(__CUDA_ARCH_FEAT_SM100_ALL)
#define HAS_TCGEN05 1
#else
#define HAS_TCGEN05 0
#endif

// ---------------- generic ptx helpers ----------------
__device__ __forceinline__ uint32_t elect_one_pred() {
    uint32_t pred;
    asm volatile(
        "{\n\t.reg .pred p;\n\t"
        "elect.sync _|p, 0xFFFFFFFF;\n\t"
        "selp.b32 %0, 1, 0, p;\n\t}"
        : "=r"(pred));
    return pred;
}

__device__ __forceinline__ uint32_t smem_u32(const void* p) {
    uint32_t a;
    asm("{ .reg .u64 t; cvta.to.shared.u64 t, %1; cvt.u32.u64 %0, t; }" : "=r"(a) : "l"(p));
    return a;
}

__device__ __forceinline__ uint32_t cluster_rank() {
    uint32_t r;
    asm("mov.u32 %0, %%cluster_ctarank;" : "=r"(r));
    return r;
}

// bf16 2-way split: x = hi + lo, hi = bf16_rn(x)
__device__ __forceinline__ void bf16_split(float x, __nv_bfloat16& h, __nv_bfloat16& l) {
    h = __float2bfloat16(x);
    l = __float2bfloat16(x - __bfloat162float(h));
}

#define MBARRIER_INIT(addr, cnt) \
    asm volatile("mbarrier.init.shared.b64 [%0], %1;" :: "r"((uint32_t)(addr)), "r"((uint32_t)(cnt)) : "memory")
#define MBARRIER_INVAL(addr) \
    asm volatile("mbarrier.inval.shared.b64 [%0];" :: "r"((uint32_t)(addr)) : "memory")

// arrive on rank0's instance of this barrier (release, cluster scope)
#define MBARRIER_ARRIVE_RANK0(local_addr) \
    asm volatile( \
        "{\n\t.reg .b32 remAddr;\n\t" \
        "mapa.shared::cluster.u32 remAddr, %0, 0;\n\t" \
        "mbarrier.arrive.shared::cluster.b64 _, [remAddr];\n\t}" \
        :: "r"((uint32_t)(local_addr)) : "memory")

// BOUNDED wait with a TIGHT budget (~250K polls): a broken protocol finishes
// fast with an observable wrong answer instead of eating the container timeout
// across the harness's many graph replays.
__device__ __forceinline__ void mbar_wait_bounded(uint32_t mbar, uint32_t parity) {
    uint32_t done = 0;
    for (int i = 0; i < 250000; ++i) {
        asm volatile(
            "{\n\t.reg .pred p;\n\t"
            "mbarrier.try_wait.parity.acquire.cta.shared::cta.b64 p, [%1], %2;\n\t"
            "selp.b32 %0, 1, 0, p;\n\t}"
            : "=r"(done) : "r"(mbar), "r"(parity) : "memory");
        if (done) break;
    }
}

#define SWZ(o) ((o) ^ (((o) >> 3) & 0x70))

__device__ __forceinline__ void cp_async16(uint32_t dst, const void* src) {
    asm volatile("cp.async.cg.shared.global [%0], [%1], 16;" :: "r"(dst), "l"(src));
}
#define CP_COMMIT() asm volatile("cp.async.commit_group;" ::: "memory")
#define CP_WAIT1()  asm volatile("cp.async.wait_group 1;" ::: "memory")
#define FENCE_PROXY_ASYNC_SHARED_CTA() asm volatile("fence.proxy.async.shared::cta;" ::: "memory")
#define CLUSTER_SYNC() do { \
    asm volatile("barrier.cluster.arrive.aligned;" ::: "memory"); \
    asm volatile("barrier.cluster.wait.aligned;" ::: "memory"); \
} while (0)

// ---------------- tcgen05 helpers (guarded, cta_group::2) ----------------
#if HAS_TCGEN05
#define TCGEN05_ALLOC_CG2(smem_result_addr, nCols) \
    asm volatile("tcgen05.alloc.cta_group::2.sync.aligned.shared::cta.b32 [%0], %1;" \
        :: "r"((uint32_t)(smem_result_addr)), "r"((uint32_t)(nCols)) : "memory")
#define TCGEN05_DEALLOC_CG2(tmem_addr, nCols) \
    asm volatile("tcgen05.dealloc.cta_group::2.sync.aligned.b32 %0, %1;" :: "r"(tmem_addr), "r"((uint32_t)(nCols)))
#define TCGEN05_RELINQUISH_CG2() \
    asm volatile("tcgen05.relinquish_alloc_permit.cta_group::2.sync.aligned;")
#define TCGEN05_COMMIT_MC_CG2(mbar_smem_addr, mask) \
    asm volatile("tcgen05.commit.cta_group::2.mbarrier::arrive::one.shared::cluster.multicast::cluster.b64 [%0], %1;" \
        :: "r"((uint32_t)(mbar_smem_addr)), "h"((uint16_t)(mask)) : "memory")
#define TCGEN05_WAIT_LD()  asm volatile("tcgen05.wait::ld.sync.aligned;" ::: "memory")
#define TCGEN05_FENCE_AFTER()  asm volatile("tcgen05.fence::after_thread_sync;" ::: "memory")
#define TCGEN05_FENCE_BEFORE() asm volatile("tcgen05.fence::before_thread_sync;" ::: "memory")

#define TCGEN05_LD_32X32B_X32(r, tmem_addr) \
    asm volatile( \
        "tcgen05.ld.sync.aligned.32x32b.x32.b32 " \
        "{%0, %1, %2, %3, %4, %5, %6, %7, " \
        " %8, %9, %10, %11, %12, %13, %14, %15, " \
        " %16, %17, %18, %19, %20, %21, %22, %23, " \
        " %24, %25, %26, %27, %28, %29, %30, %31}, [%32];" \
        : "=r"((r)[0]),  "=r"((r)[1]),  "=r"((r)[2]),  "=r"((r)[3]), \
          "=r"((r)[4]),  "=r"((r)[5]),  "=r"((r)[6]),  "=r"((r)[7]), \
          "=r"((r)[8]),  "=r"((r)[9]),  "=r"((r)[10]), "=r"((r)[11]), \
          "=r"((r)[12]), "=r"((r)[13]), "=r"((r)[14]), "=r"((r)[15]), \
          "=r"((r)[16]), "=r"((r)[17]), "=r"((r)[18]), "=r"((r)[19]), \
          "=r"((r)[20]), "=r"((r)[21]), "=r"((r)[22]), "=r"((r)[23]), \
          "=r"((r)[24]), "=r"((r)[25]), "=r"((r)[26]), "=r"((r)[27]), \
          "=r"((r)[28]), "=r"((r)[29]), "=r"((r)[30]), "=r"((r)[31]) \
        : "r"(tmem_addr))

// bf16 cg2 SS MMA (kind::f16) with disable-output-lane vector (8 regs, all 0)
__device__ __forceinline__ void tcgen05_mma_bf16_cg2(uint32_t d, uint64_t ad, uint64_t bd,
                                                     uint32_t idesc, uint32_t en) {
    asm volatile(
        "{\n\t.reg .pred p;\n\t"
        "setp.ne.u32 p, %5, 0;\n\t"
        "tcgen05.mma.cta_group::2.kind::f16 [%0], %1, %2, %3, "
        "{%4, %4, %4, %4, %4, %4, %4, %4}, p;\n\t}"
        :: "r"(d), "l"(ad), "l"(bd), "r"(idesc), "r"(0u), "r"(en) : "memory");
}
#endif // HAS_TCGEN05

static constexpr uint64_t SMEM_DESC_BASE_SW128 =
    (uint64_t(2) << 61) | (uint64_t(1) << 46) | (uint64_t(64) << 32) | (uint64_t(1) << 16);
#define MAKE_SMEM_DESC(base_addr) (SMEM_DESC_BASE_SW128 | ((uint64_t)((base_addr) >> 4) & 0x3FFF))

// ---------------- scratch (static device globals; 256B-aligned for cp.async) ----------------
__device__ __align__(256) float g_q  [(size_t)B * S * NH  * HD];
__device__ __align__(256) float g_k  [(size_t)B * S * NKV * HD];
__device__ __align__(256) float g_v  [(size_t)B * S * NKV * HD];
__device__ __align__(256) float g_phi[(size_t)B * S * NH  * HD];
__device__ __align__(256) float g_Qg [B * NH * HD];
__device__ __align__(256) float g_logits[B * NH * S];
__device__ __align__(256) float g_alpha [B * NH * S];
__device__ __align__(256) float g_M  [B * NH * HD * HD];
// bf16 hi/lo split of the GEMM A operand (hs for projections, then ctx for Wo)
__device__ __align__(256) __nv_bfloat16 g_Ahi[(size_t)BS_ROWS * HID];
__device__ __align__(256) __nv_bfloat16 g_Alo[(size_t)BS_ROWS * HID];
// transposed + split weights: [N, K] K-major, bf16 hi/lo
__device__ __align__(256) __nv_bfloat16 g_WqT_hi  [HID * HID];
__device__ __align__(256) __nv_bfloat16 g_WqT_lo  [HID * HID];
__device__ __align__(256) __nv_bfloat16 g_WkT_hi  [512 * HID];
__device__ __align__(256) __nv_bfloat16 g_WkT_lo  [512 * HID];
__device__ __align__(256) __nv_bfloat16 g_WvT_hi  [512 * HID];
__device__ __align__(256) __nv_bfloat16 g_WvT_lo  [512 * HID];
__device__ __align__(256) __nv_bfloat16 g_WphiT_hi[HID * HID];
__device__ __align__(256) __nv_bfloat16 g_WphiT_lo[HID * HID];
__device__ __align__(256) __nv_bfloat16 g_WoT_hi  [HID * HID];
__device__ __align__(256) __nv_bfloat16 g_WoT_lo  [HID * HID];

// ---------------- cg2 3-term bf16 GEMM ---------------------------------------
// Pair tile: M=256 (128 A-rows per CTA), N=256 (128 B-rows per CTA, split).
// K staged 64 bf16 (128B rows), 3-stage cp.async ring, look-ahead 2. 256 thr/CTA.
#define ROWS_CTA 128
#define PAIR_M 256
#define PAIR_N 256
#define STAGES 3
#define REGION_BYTES (ROWS_CTA * 128)         // 16KB (one of A/B hi/lo)
#define STAGE_BYTES (4 * REGION_BYTES)        // 64KB
#define SM_FULL(s)  (8  + (s) * 8)            // rank1->rank0 readiness
#define SM_EMPTY(s) (32 + (s) * 8)            // MMA-done (multicast)
#define SM_DONE 56
#define SM_AHI(s) (1024 + (s) * STAGE_BYTES)
#define SM_ALO(s) (SM_AHI(s) + REGION_BYTES)
#define SM_BHI(s) (SM_AHI(s) + 2 * REGION_BYTES)
#define SM_BLO(s) (SM_AHI(s) + 3 * REGION_BYTES)
#define SMEM_GEMM (1024 + STAGES * STAGE_BYTES)   // 197632 bytes

// idesc for kind::f16 bf16 (validated in test_2cta_mma_bf16):
static constexpr uint32_t IDESC_CG2 =
    (1u << 4)              // dtype F32
  | (1u << 7)              // atype BF16
  | (1u << 10)             // btype BF16
  | ((PAIR_N / 8) << 17)   // N = 256
  | ((PAIR_M / 16) << 24); // M = 256

__device__ __forceinline__ void load_region(uint32_t dst, const __nv_bfloat16* __restrict__ src,
                                            int row0, int k0, int tid) {
    #pragma unroll
    for (int i = 0; i < 4; i++) {                 // 128 rows x 8 chunks(16B=8 elts) = 1024
        int chunk = i * 256 + tid;
        int row = chunk >> 3, c = chunk & 7;
        uint32_t off = (uint32_t)(row * 128 + c * 16);
        cp_async16(dst + SWZ(off), src + (size_t)(row0 + row) * GK + k0 + c * 8);
    }
}

__device__ __forceinline__ void load_stage(uint32_t sb, int st,
                                           const __nv_bfloat16* __restrict__ Ahi,
                                           const __nv_bfloat16* __restrict__ Alo,
                                           const __nv_bfloat16* __restrict__ Bhi,
                                           const __nv_bfloat16* __restrict__ Blo,
                                           int aRow0, int bRow0, int k0, int tid) {
    load_region(sb + SM_AHI(st), Ahi, aRow0, k0, tid);
    load_region(sb + SM_ALO(st), Alo, aRow0, k0, tid);
    load_region(sb + SM_BHI(st), Bhi, bRow0, k0, tid);
    load_region(sb + SM_BLO(st), Blo, bRow0, k0, tid);
}

__global__ __launch_bounds__(256, 1) __cluster_dims__(2, 1, 1)
void tc_gemm(const __nv_bfloat16* __restrict__ Ahi, const __nv_bfloat16* __restrict__ Alo,
             const __nv_bfloat16* __restrict__ Bhi, const __nv_bfloat16* __restrict__ Blo,
             float* __restrict__ C, int N) {
    const uint32_t rank = cluster_rank();
    const int m0 = blockIdx.z * PAIR_M;
    const int n0 = blockIdx.y * PAIR_N;
#if HAS_TCGEN05
    extern __shared__ char smem[];
    uint32_t sb = smem_u32(smem);
    const int tid = threadIdx.x;
    const int wid = tid >> 5, lid = tid & 31;
    const int aRow0 = m0 + (int)rank * ROWS_CTA;
    const int bRow0 = n0 + (int)rank * ROWS_CTA;

    if (tid == 0) {
        #pragma unroll
        for (int s = 0; s < STAGES; s++) {
            MBARRIER_INIT(sb + SM_FULL(s), 1);
            MBARRIER_INIT(sb + SM_EMPTY(s), 1);
        }
        MBARRIER_INIT(sb + SM_DONE, 1);
    }
    __syncthreads();
    if (wid == 0) TCGEN05_ALLOC_CG2(sb, 256);
    __syncthreads();
    uint32_t tbase;
    asm volatile("ld.shared.b32 %0, [%1];" : "=r"(tbase) : "r"(sb));

    // prologue: load stages 0 and 1 (look-ahead 2)
    load_stage(sb, 0, Ahi, Alo, Bhi, Blo, aRow0, bRow0, 0, tid);
    CP_COMMIT();
    load_stage(sb, 1, Ahi, Alo, Bhi, Blo, aRow0, bRow0, 64, tid);
    CP_COMMIT();

    CLUSTER_SYNC();   // barriers visible cluster-wide before cross-CTA signaling

    for (int kt = 0; kt < KITERS; ++kt) {
        const int st = kt % STAGES;
        CP_WAIT1();                 // my load(kt) landed
        __syncthreads();

        if (rank == 1) {
            if (wid == 0 && elect_one_pred()) {
                FENCE_PROXY_ASYNC_SHARED_CTA();
                MBARRIER_ARRIVE_RANK0(sb + SM_FULL(st));   // my tile st ready
            }
        } else {
            if (wid == 0) {
                mbar_wait_bounded(sb + SM_FULL(st), (uint32_t)((kt / 3) & 1));
                if (elect_one_pred()) {
                    FENCE_PROXY_ASYNC_SHARED_CTA();
                    uint64_t ahi = MAKE_SMEM_DESC(sb + SM_AHI(st));
                    uint64_t alo = MAKE_SMEM_DESC(sb + SM_ALO(st));
                    uint64_t bhi = MAKE_SMEM_DESC(sb + SM_BHI(st));
                    uint64_t blo = MAKE_SMEM_DESC(sb + SM_BLO(st));
                    #pragma unroll
                    for (int s8 = 0; s8 < 4; s8++) {       // 4 K-steps of 16 bf16
                        uint64_t o = (uint64_t)(s8 * 2);
                        tcgen05_mma_bf16_cg2(tbase, ahi + o, bhi + o, IDESC_CG2,
                                             (kt == 0 && s8 == 0) ? 0u : 1u);
                        tcgen05_mma_bf16_cg2(tbase, ahi + o, blo + o, IDESC_CG2, 1u);
                        tcgen05_mma_bf16_cg2(tbase, alo + o, bhi + o, IDESC_CG2, 1u);
                    }
                    TCGEN05_COMMIT_MC_CG2(sb + SM_EMPTY(st), 0x3);
                }
            }
        }

        // refill: buffer (kt+2)%3 was read by MMA(kt-1) -> wait its EMPTY commit
        if (kt + 2 < KITERS) {
            int ld = (kt + 2) % STAGES;
            if (kt >= 1)
                mbar_wait_bounded(sb + SM_EMPTY(ld), (uint32_t)(((kt - 1) / 3) & 1));
            load_stage(sb, ld, Ahi, Alo, Bhi, Blo, aRow0, bRow0, (kt + 2) * 64, tid);
        }
        CP_COMMIT();   // unconditional: keeps group count constant
    }

    if (rank == 0 && wid == 0) {
        if (elect_one_pred()) TCGEN05_COMMIT_MC_CG2(sb + SM_DONE, 0x3);
    }
    mbar_wait_bounded(sb + SM_DONE, 0);
    TCGEN05_FENCE_AFTER();

    // epilogue: warps 0-3 read 128 lanes x 256 cols from this CTA's TMEM
    if (wid < 4) {
        int row = m0 + (int)rank * ROWS_CTA + wid * 32 + lid;
        float* crow = C + (size_t)row * N + n0;
        for (int c0 = 0; c0 < PAIR_N; c0 += 32) {
            uint32_t r[32];
            TCGEN05_LD_32X32B_X32(r, tbase + c0);
            TCGEN05_WAIT_LD();
            #pragma unroll
            for (int j = 0; j < 32; j += 4) {
                float4 v = make_float4(__uint_as_float(r[j]),     __uint_as_float(r[j + 1]),
                                       __uint_as_float(r[j + 2]), __uint_as_float(r[j + 3]));
                *(float4*)(crow + c0 + j) = v;
            }
        }
        TCGEN05_FENCE_BEFORE();
    }
    __syncthreads();
    if (tid == 0) {
        #pragma unroll
        for (int s = 0; s < STAGES; s++) {
            MBARRIER_INVAL(sb + SM_FULL(s));
            MBARRIER_INVAL(sb + SM_EMPTY(s));
        }
        MBARRIER_INVAL(sb + SM_DONE);
    }
    __syncthreads();
    if (wid == 0) {
        TCGEN05_RELINQUISH_CG2();
        TCGEN05_DEALLOC_CG2(tbase, 256);
    }
    CLUSTER_SYNC();
#else
    // Fallback for the non-'a' target: correct (slow) per-element GEMM.
    for (int idx = threadIdx.x; idx < ROWS_CTA * PAIR_N; idx += blockDim.x) {
        int m = m0 + (int)rank * ROWS_CTA + idx / PAIR_N;
        int n = n0 + idx % PAIR_N;
        const __nv_bfloat16* ah = Ahi + (size_t)m * GK;
        const __nv_bfloat16* al = Alo + (size_t)m * GK;
        const __nv_bfloat16* bh = Bhi + (size_t)n * GK;
        const __nv_bfloat16* bl = Blo + (size_t)n * GK;
        float acc = 0.0f;
        for (int k = 0; k < GK; ++k)
            acc = fmaf(__bfloat162float(ah[k]) + __bfloat162float(al[k]),
                       __bfloat162float(bh[k]) + __bfloat162float(bl[k]), acc);
        C[(size_t)m * N + n] = acc;
    }
#endif
}

// ---------------- split: fp32 -> bf16 hi/lo ----------------
__global__ __launch_bounds__(256) void split_kernel(const float* __restrict__ in,
                                                    __nv_bfloat16* __restrict__ hi,
                                                    __nv_bfloat16* __restrict__ lo, long n4) {
    long i = (long)blockIdx.x * blockDim.x + threadIdx.x;
    if (i >= n4) return;
    float4 x = ((const float4*)in)[i];
    __nv_bfloat16 h0, h1, h2, h3, l0, l1, l2, l3;
    bf16_split(x.x, h0, l0);
    bf16_split(x.y, h1, l1);
    bf16_split(x.z, h2, l2);
    bf16_split(x.w, h3, l3);
    __nv_bfloat162* hi2 = (__nv_bfloat162*)hi;
    __nv_bfloat162* lo2 = (__nv_bfloat162*)lo;
    hi2[2 * i]     = __halves2bfloat162(h0, h1);
    hi2[2 * i + 1] = __halves2bfloat162(h2, h3);
    lo2[2 * i]     = __halves2bfloat162(l0, l1);
    lo2[2 * i + 1] = __halves2bfloat162(l2, l3);
}

// ---------------- transpose + split to bf16 hi/lo ----------------
__global__ __launch_bounds__(256) void transpose_split_kernel(const float* __restrict__ in,
                                                              __nv_bfloat16* __restrict__ out_hi,
                                                              __nv_bfloat16* __restrict__ out_lo,
                                                              int R, int Ccols) {
    __shared__ float t[32][33];
    int c0 = blockIdx.x * 32, r0 = blockIdx.y * 32;
    int x = threadIdx.x & 31, y = (threadIdx.x >> 5) * 4;
    #pragma unroll
    for (int i = 0; i < 4; i++)
        t[y + i][x] = in[(size_t)(r0 + y + i) * Ccols + c0 + x];
    __syncthreads();
    #pragma unroll
    for (int i = 0; i < 4; i++) {
        float v = t[x][y + i];
        __nv_bfloat16 h, l;
        bf16_split(v, h, l);
        size_t o = (size_t)(c0 + y + i) * R + r0 + x;
        out_hi[o] = h;
        out_lo[o] = l;
    }
}

// ---------------- fused RoPE + kappa ----------------
__global__ void rope_kappa_kernel(float* __restrict__ x, int H, long total_pairs) {
    long idx = (long)blockIdx.x * blockDim.x + threadIdx.x;
    if (idx >= total_pairs) return;
    int j = (int)(idx & 31);
    long t = idx >> 5;
    int h = (int)(t % H); t /= H;
    int s = (int)(t % S);
    int b = (int)(t / S);

    float e = (float)(2 * j) / 64.0f;
    float invf = 1.0f / powf(10000.0f, e);
    float ang = (float)s * invf;
    float c, sn;
    sincosf(ang, &sn, &c);

    size_t base = (((size_t)b * S + s) * H + h) * 64;
    float x1 = x[base + j];
    float x2 = x[base + j + 32];
    float o1 = x1 * c - x2 * sn;
    float o2 = x2 * c + x1 * sn;
    o1 = (o1 > 0.0f) ? (o1 + 1.0f) : expf(o1);
    o2 = (o2 > 0.0f) ? (o2 + 1.0f) : expf(o2);
    x[base + j]      = o1;
    x[base + j + 32] = o2;
}

// ---------------- Qg = mean over S of Qk ----------------
__global__ __launch_bounds__(256) void qg_kernel() {
    int bh = blockIdx.x;
    int b = bh / NH, h = bh % NH;
    int d  = threadIdx.x % 64;
    int sg = threadIdx.x / 64;
    float sum = 0.0f;
    for (int s = sg; s < S; s += 4)
        sum += g_q[(((size_t)b * S + s) * NH + h) * 64 + d];
    __shared__ float red[256];
    red[threadIdx.x] = sum;
    __syncthreads();
    if (sg == 0) {
        float tot = red[d] + red[64 + d] + red[128 + d] + red[192 + d];
        g_Qg[bh * 64 + d] = tot / (float)S;
    }
}

// ---------------- logits ----------------
__global__ __launch_bounds__(256) void logits_kernel() {
    int warp = (blockIdx.x * blockDim.x + threadIdx.x) >> 5;
    int lane = threadIdx.x & 31;
    int s = warp % S; int t = warp / S;
    int h = t % NH;   int b = t / NH;
    int hk = h / GROUPS;
    const float* krow = &g_k[(((size_t)b * S + s) * NKV + hk) * 64];
    const float* qrow = &g_Qg[(b * NH + h) * 64];
    float sum = krow[lane] * qrow[lane] + krow[lane + 32] * qrow[lane + 32];
    #pragma unroll
    for (int off = 16; off > 0; off >>= 1)
        sum += __shfl_xor_sync(0xffffffffu, sum, off);
    if (lane == 0)
        g_logits[((size_t)b * NH + h) * S + s] = sum;
}

// ---------------- softmax * S ----------------
__global__ __launch_bounds__(256) void softmax_kernel() {
    int bh = blockIdx.x;
    const float* row = &g_logits[(size_t)bh * S];
    __shared__ float red[256];
    float m = -INFINITY;
    for (int i = threadIdx.x; i < S; i += 256) m = fmaxf(m, row[i]);
    red[threadIdx.x] = m; __syncthreads();
    for (int st = 128; st > 0; st >>= 1) {
        if (threadIdx.x < st) red[threadIdx.x] = fmaxf(red[threadIdx.x], red[threadIdx.x + st]);
        __syncthreads();
    }
    m = red[0]; __syncthreads();
    float sum = 0.0f;
    for (int i = threadIdx.x; i < S; i += 256) sum += expf(row[i] - m);
    red[threadIdx.x] = sum; __syncthreads();
    for (int st = 128; st > 0; st >>= 1) {
        if (threadIdx.x < st) red[threadIdx.x] += red[threadIdx.x + st];
        __syncthreads();
    }
    float scale = (float)S / red[0];
    for (int i = threadIdx.x; i < S; i += 256)
        g_alpha[(size_t)bh * S + i] = expf(row[i] - m) * scale;
}

// ---------------- zero g_M ----------------
__global__ __launch_bounds__(256) void zeroM_kernel() {
    int i = blockIdx.x * 256 + threadIdx.x;
    ((float4*)g_M)[i] = make_float4(0.f, 0.f, 0.f, 0.f);
}

// ---------------- outer_sum state (split over S, atomic accumulate) ----------------
#define SCHUNK 8
__global__ __launch_bounds__(256) void outer_kernel() {
    int bh = blockIdx.x;
    int sc = blockIdx.y;
    int b = bh / NH, h = bh % NH, hk = h / GROUPS;
    __shared__ float Ws[32][64];
    __shared__ float Vs[32][64];
    int f = threadIdx.x % 64;
    int g = threadIdx.x / 64;
    float acc[16];
    #pragma unroll
    for (int i = 0; i < 16; i++) acc[i] = 0.0f;

    int sBeg = sc * (S / SCHUNK), sEnd = sBeg + (S / SCHUNK);
    for (int s0 = sBeg; s0 < sEnd; s0 += 32) {
        __syncthreads();
        for (int i = threadIdx.x; i < 32 * 64; i += 256) {
            int s = i / 64, d = i % 64;
            size_t idx = (((size_t)b * S + s0 + s) * NKV + hk) * 64 + d;
            float a = g_alpha[((size_t)b * NH + h) * S + s0 + s];
            Ws[s][d] = a * g_k[idx];
            Vs[s][d] = g_v[idx];
        }
        __syncthreads();
        #pragma unroll 4
        for (int s = 0; s < 32; s++) {
            float vv = Vs[s][f];
            #pragma unroll
            for (int i = 0; i < 16; i++)
                acc[i] = fmaf(Ws[s][g + 4 * i], vv, acc[i]);
        }
    }
    #pragma unroll
    for (int i = 0; i < 16; i++) {
        int d = g + 4 * i;
        atomicAdd(&g_M[((size_t)bh * 64 + d) * 64 + f], acc[i]);
    }
}

// ---------------- ctx = phi * (Qk . M), fused bf16 split into g_Ahi/g_Alo ----------------
__global__ __launch_bounds__(256) void attnmul_kernel() {
    int bh = blockIdx.y;
    int b = bh / NH, h = bh % NH;
    int s0 = blockIdx.x * 64;
    __shared__ float Ms[64][64];
    __shared__ float Qs[64][64];
    for (int i = threadIdx.x; i < 64 * 64; i += 256) {
        Ms[i / 64][i % 64] = g_M[(size_t)bh * 4096 + i];
        int s = i / 64, d = i % 64;
        Qs[s][d] = g_q[(((size_t)b * S + s0 + s) * NH + h) * 64 + d];
    }
    __syncthreads();
    int f = threadIdx.x % 64;
    int sg = threadIdx.x / 64;
    for (int s = sg; s < 64; s += 4) {
        float acc = 0.0f;
        #pragma unroll
        for (int d = 0; d < 64; d++)
            acc = fmaf(Qs[s][d], Ms[d][f], acc);
        size_t idx = (((size_t)b * S + s0 + s) * NH + h) * 64 + f;
        float v = g_phi[idx] * acc;
        __nv_bfloat16 hh, ll;
        bf16_split(v, hh, ll);
        g_Ahi[idx] = hh;       // [B*S, 2048] row-major: row=(b*S+s), col=h*64+f
        g_Alo[idx] = ll;
    }
}

// ---------------- host launcher ----------------
extern "C" void kernel_launch(void* const* d_in, const int* in_sizes, int n_in,
                              void* d_out, int out_size) {
    const float* hs   = (const float*)d_in[0];
    const float* Wq   = (const float*)d_in[1];
    const float* Wk   = (const float*)d_in[2];
    const float* Wv   = (const float*)d_in[3];
    const float* Wphi = (const float*)d_in[4];
    const float* Wo   = (const float*)d_in[5];
    float* out = (float*)d_out;

    float *q, *k, *v, *phi;
    __nv_bfloat16 *Ahi, *Alo;
    __nv_bfloat16 *WqTh, *WqTl, *WkTh, *WkTl, *WvTh, *WvTl, *WpTh, *WpTl, *WoTh, *WoTl;
    cudaGetSymbolAddress((void**)&q,    g_q);
    cudaGetSymbolAddress((void**)&k,    g_k);
    cudaGetSymbolAddress((void**)&v,    g_v);
    cudaGetSymbolAddress((void**)&phi,  g_phi);
    cudaGetSymbolAddress((void**)&Ahi,  g_Ahi);
    cudaGetSymbolAddress((void**)&Alo,  g_Alo);
    cudaGetSymbolAddress((void**)&WqTh, g_WqT_hi);
    cudaGetSymbolAddress((void**)&WqTl, g_WqT_lo);
    cudaGetSymbolAddress((void**)&WkTh, g_WkT_hi);
    cudaGetSymbolAddress((void**)&WkTl, g_WkT_lo);
    cudaGetSymbolAddress((void**)&WvTh, g_WvT_hi);
    cudaGetSymbolAddress((void**)&WvTl, g_WvT_lo);
    cudaGetSymbolAddress((void**)&WpTh, g_WphiT_hi);
    cudaGetSymbolAddress((void**)&WpTl, g_WphiT_lo);
    cudaGetSymbolAddress((void**)&WoTh, g_WoT_hi);
    cudaGetSymbolAddress((void**)&WoTl, g_WoT_lo);

    cudaFuncSetAttribute(tc_gemm, cudaFuncAttributeMaxDynamicSharedMemorySize, SMEM_GEMM);

    // transpose + split all weights to bf16 hi/lo [N, K]
    transpose_split_kernel<<<dim3(HID / 32, HID / 32), 256>>>(Wq,   WqTh, WqTl, HID, HID);
    transpose_split_kernel<<<dim3(512 / 32, HID / 32), 256>>>(Wk,   WkTh, WkTl, HID, 512);
    transpose_split_kernel<<<dim3(512 / 32, HID / 32), 256>>>(Wv,   WvTh, WvTl, HID, 512);
    transpose_split_kernel<<<dim3(HID / 32, HID / 32), 256>>>(Wphi, WpTh, WpTl, HID, HID);
    transpose_split_kernel<<<dim3(HID / 32, HID / 32), 256>>>(Wo,   WoTh, WoTl, HID, HID);

    // split hidden_states -> Ahi/Alo
    {
        long n4 = (long)BS_ROWS * HID / 4;
        split_kernel<<<(unsigned)((n4 + 255) / 256), 256>>>(hs, Ahi, Alo, n4);
    }

    // projections: cluster pairs — grid (2, N/256, M/256)
    dim3 gBig(2, HID / PAIR_N, BS_ROWS / PAIR_M);   // (2, 8, 32)
    dim3 gKV (2, 512 / PAIR_N, BS_ROWS / PAIR_M);   // (2, 2, 32)
    tc_gemm<<<gBig, 256, SMEM_GEMM>>>(Ahi, Alo, WqTh, WqTl, q,   HID);
    tc_gemm<<<gKV,  256, SMEM_GEMM>>>(Ahi, Alo, WkTh, WkTl, k,   512);
    tc_gemm<<<gKV,  256, SMEM_GEMM>>>(Ahi, Alo, WvTh, WvTl, v,   512);
    tc_gemm<<<gBig, 256, SMEM_GEMM>>>(Ahi, Alo, WpTh, WpTl, phi, HID);

    // rope + kappa
    {
        long qp = (long)B * S * NH * 32;
        rope_kappa_kernel<<<(unsigned)((qp + 255) / 256), 256>>>(q, NH, qp);
        long kp = (long)B * S * NKV * 32;
        rope_kappa_kernel<<<(unsigned)((kp + 255) / 256), 256>>>(k, NKV, kp);
    }

    qg_kernel<<<B * NH, 256>>>();
    logits_kernel<<<(B * NH * S) / 8, 256>>>();
    softmax_kernel<<<B * NH, 256>>>();
    zeroM_kernel<<<(B * NH * HD * HD) / 1024, 256>>>();
    outer_kernel<<<dim3(B * NH, SCHUNK), 256>>>();
    attnmul_kernel<<<dim3(S / 64, B * NH), 256>>>();   // writes bf16 ctx hi/lo directly

    // output projection
    tc_gemm<<<gBig, 256, SMEM_GEMM>>>(Ahi, Alo, WoTh, WoTl, out, HID);
}